// round 7
// baseline (speedup 1.0000x reference)
#include <cuda_runtime.h>
#include <cuda_bf16.h>
#include <math.h>
#include <stdint.h>

// Problem constants
#define Tn 16384            // B*N tokens
#define Dd 768
#define Ff 3072
#define Ee 16
#define CAPc 160
#define Bbat 8
#define Nseq 2048
#define LCAP 320            // max list entries per (b,e) (<= 2*CAPc)

// Output layout (float32, concatenated in reference return order)
#define OFF_AUX    12582912
#define OFF_BAL    12582913
#define OFF_ZL     12582914
#define OFF_LOGITS 12582915ll
#define OFF_ENERGY 12845059ll
#define OFF_GIDX   12861443ll

// ---------------- scratch (device globals; no runtime allocation) ----------------
__device__ float g_wi[(size_t)Tn * Dd];               // RMS-normed input (fp32)
__device__ float g_h [(size_t)Tn * Ff];               // h (fp32)
__device__ __nv_bfloat16 g_A1[(size_t)Tn * 2 * Dd];   // [wi_hi | wi_lo]
__device__ __nv_bfloat16 g_B1[(size_t)Ff * 2 * Dd];   // [Wi_hi | Wi_lo]
__device__ __nv_bfloat16 g_A2[(size_t)Tn * 2 * Ff];   // [h_hi  | h_lo]
__device__ __nv_bfloat16 g_B2[(size_t)Dd * 2 * Ff];   // [Wo_hi | Wo_lo]
__device__ int   g_e  [2 * Tn];
__device__ float g_gate[2 * Tn];
__device__ float g_gp  [2 * Tn];                      // gate after drop (0 if dropped)
__device__ int   g_sh1 [Tn];
__device__ float g_dp[Bbat * Ee];
__device__ float g_d1[Bbat * Ee];
__device__ float g_zl;
// per-(b,e) alive token lists: [k0 entries | k1 entries]
__device__ int   g_ltok [Bbat * Ee * LCAP];
__device__ float g_lg   [Bbat * Ee * LCAP];
__device__ int   g_lcnt0[Bbat * Ee];                  // k0 count
__device__ int   g_lcnt [Bbat * Ee];                  // total count
__device__ float g_u1[Bbat * Ee * LCAP * 16];         // u per list entry (wi path)
__device__ float g_u2[Bbat * Ee * LCAP * 16];         // u per list entry (wo path)

// ---------------- PTX helpers (sm_100-safe) ----------------
__device__ __forceinline__ uint32_t s2u(const void* p) {
    uint32_t a;
    asm("{ .reg .u64 t; cvta.to.shared.u64 t, %1; cvt.u32.u64 %0, t; }" : "=r"(a) : "l"(p));
    return a;
}
__device__ __forceinline__ void cpa16(uint32_t s, const void* g) {
    asm volatile("cp.async.cg.shared.global [%0], [%1], 16;\n" :: "r"(s), "l"(g));
}
#define CPA_COMMIT() asm volatile("cp.async.commit_group;\n" ::: "memory")
#define CPA_WAIT2()  asm volatile("cp.async.wait_group 2;\n" ::: "memory")

__device__ __forceinline__ void ldsm4(uint32_t* r, uint32_t a) {
    asm volatile("ldmatrix.sync.aligned.m8n8.x4.shared.b16 {%0,%1,%2,%3}, [%4];"
                 : "=r"(r[0]), "=r"(r[1]), "=r"(r[2]), "=r"(r[3]) : "r"(a));
}
__device__ __forceinline__ void mma16816(float* c, const uint32_t* a, uint32_t b0, uint32_t b1) {
    asm volatile("mma.sync.aligned.m16n8k16.row.col.f32.bf16.bf16.f32 "
                 "{%0,%1,%2,%3}, {%4,%5,%6,%7}, {%8,%9}, {%0,%1,%2,%3};"
                 : "+f"(c[0]), "+f"(c[1]), "+f"(c[2]), "+f"(c[3])
                 : "r"(a[0]), "r"(a[1]), "r"(a[2]), "r"(a[3]), "r"(b0), "r"(b1));
}

#define SWZ(o) ((o) ^ (((o) >> 3) & 0x70))

// GEMM smem: A stages [128][64]bf16 = 16KB (x4), B stages [256][64]bf16 = 32KB (x4)
#define SM_A(s) ((s) * 16384)
#define SM_B(s) (65536 + (s) * 32768)
#define SMEM_GEMM 196608

#define SMEM_BIG  196608    // 16*3072 floats (Bi / Ao buffers)
#define SMEM_SML  49152     // 16*768 floats (Ai / Bo buffers)

// ---------------- stage loader: chunk c of the 3-term schedule over 2-term storage ----
__device__ __forceinline__ void load_stage(uint32_t sb, int s,
                                           const __nv_bfloat16* __restrict__ A,
                                           const __nv_bfloat16* __restrict__ B,
                                           int bm, int bn, int c, int cpt, int K, int tid) {
    int t = c / cpt;
    int kc = (c - t * cpt) * 64;
    int aoff = (t == 1) ? K : 0;   // A terms: hi, lo, hi
    int boff = (t == 2) ? K : 0;   // B terms: hi, hi, lo
    const int K2 = 2 * K;
    #pragma unroll
    for (int j = 0; j < 2; j++) {
        int idx = tid + 512 * j, row = idx >> 3, seg = idx & 7;
        cpa16(sb + SM_A(s) + SWZ(row * 128 + seg * 16),
              A + (size_t)(bm + row) * K2 + aoff + kc + seg * 8);
    }
    #pragma unroll
    for (int j = 0; j < 4; j++) {
        int idx = tid + 512 * j, row = idx >> 3, seg = idx & 7;
        cpa16(sb + SM_B(s) + SWZ(row * 128 + seg * 16),
              B + (size_t)(bn + row) * K2 + boff + kc + seg * 8);
    }
}

// ---------------- mma.sync split-bf16 GEMM with fused epilogues ----------------
// mode 1: C = relu(z) + gs*z         (GEMM1 -> h)
// mode 2: C = x + (1+gs)*z           (GEMM2 -> out)
__global__ __launch_bounds__(512, 1)
void k_tc_gemm(const __nv_bfloat16* __restrict__ A, const __nv_bfloat16* __restrict__ B,
               float* __restrict__ C, int Ncols, int K, int cpt, int KI,
               int mode, const float* __restrict__ x) {
    extern __shared__ char smem[];
    const uint32_t sb = s2u(smem);
    const int tid = threadIdx.x;
    const int wid = tid >> 5;
    const int lane = tid & 31;
    const int warp_m = wid & 3;
    const int warp_n = wid >> 2;
    const int bm = blockIdx.y * 128;
    const int bn = blockIdx.x * 256;

    float acc[2][8][4];
    #pragma unroll
    for (int i = 0; i < 2; i++)
        #pragma unroll
        for (int j = 0; j < 8; j++)
            #pragma unroll
            for (int q = 0; q < 4; q++) acc[i][j][q] = 0.f;

    #pragma unroll
    for (int c = 0; c < 3; c++) {
        load_stage(sb, c, A, B, bm, bn, c, cpt, K, tid);
        CPA_COMMIT();
    }

    for (int i = 0; i < KI; i++) {
        const int si = i & 3;
        CPA_WAIT2();
        __syncthreads();

        const int j = i + 3;
        if (j < KI) load_stage(sb, j & 3, A, B, bm, bn, j, cpt, K, tid);
        CPA_COMMIT();

        const uint32_t sa = sb + SM_A(si);
        const uint32_t sB = sb + SM_B(si);
        #pragma unroll
        for (int ks = 0; ks < 4; ks++) {
            uint32_t a[2][4];
            #pragma unroll
            for (int mt = 0; mt < 2; mt++) {
                int row = warp_m * 32 + mt * 16 + (lane & 15);
                ldsm4(a[mt], sa + SWZ(row * 128 + ks * 32 + ((lane >> 4) << 4)));
            }
            uint32_t b[4][4];
            #pragma unroll
            for (int g = 0; g < 4; g++) {
                int nr = warp_n * 64 + g * 16 + ((lane >> 4) << 3) + (lane & 7);
                ldsm4(b[g], sB + SWZ(nr * 128 + ks * 32 + (((lane >> 3) & 1) << 4)));
            }
            #pragma unroll
            for (int mt = 0; mt < 2; mt++)
                #pragma unroll
                for (int nt = 0; nt < 8; nt++) {
                    int g = nt >> 1, hf = (nt & 1) << 1;
                    mma16816(acc[mt][nt], a[mt], b[g][hf], b[g][hf + 1]);
                }
        }
        __syncthreads();
    }

    #pragma unroll
    for (int mt = 0; mt < 2; mt++) {
        int r0 = bm + warp_m * 32 + mt * 16 + (lane >> 2);
        float gs0 = g_gp[r0] + g_gp[Tn + r0];
        float gs8 = g_gp[r0 + 8] + g_gp[Tn + r0 + 8];
        #pragma unroll
        for (int nt = 0; nt < 8; nt++) {
            int col = bn + warp_n * 64 + nt * 8 + (lane & 3) * 2;
            float v0 = acc[mt][nt][0], v1 = acc[mt][nt][1];
            float v2 = acc[mt][nt][2], v3 = acc[mt][nt][3];
            float* c0 = C + (size_t)r0 * Ncols + col;
            float* c8 = C + (size_t)(r0 + 8) * Ncols + col;
            if (mode == 1) {
                *(float2*)c0 = make_float2(fmaxf(v0, 0.f) + gs0 * v0, fmaxf(v1, 0.f) + gs0 * v1);
                *(float2*)c8 = make_float2(fmaxf(v2, 0.f) + gs8 * v2, fmaxf(v3, 0.f) + gs8 * v3);
            } else {
                float2 x0 = *(const float2*)(x + (size_t)r0 * Ncols + col);
                float2 x8 = *(const float2*)(x + (size_t)(r0 + 8) * Ncols + col);
                *(float2*)c0 = make_float2(x0.x + (1.f + gs0) * v0, x0.y + (1.f + gs0) * v1);
                *(float2*)c8 = make_float2(x8.x + (1.f + gs8) * v2, x8.y + (1.f + gs8) * v3);
            }
        }
    }
}

// ---------------- init ----------------
__global__ void k_init() {
    int i = threadIdx.x;
    if (i < Bbat * Ee) g_dp[i] = 0.f;
    if (i == 0) g_zl = 0.f;
}

// ---------------- RMS norm (+ split-bf16 A1 build, [hi|lo]) ----------------
__global__ __launch_bounds__(256) void k_rms(const float* __restrict__ x,
                                             const float* __restrict__ lnw) {
    int t = blockIdx.x;
    const float* xr = x + (size_t)t * Dd;
    float s = 0.f;
    for (int d = threadIdx.x; d < Dd; d += 256) { float v = xr[d]; s += v * v; }
    __shared__ float red[256];
    red[threadIdx.x] = s; __syncthreads();
    for (int o = 128; o > 0; o >>= 1) {
        if (threadIdx.x < o) red[threadIdx.x] += red[threadIdx.x + o];
        __syncthreads();
    }
    float inv = rsqrtf(red[0] / (float)Dd + 1e-6f);
    __nv_bfloat16* a1 = g_A1 + (size_t)t * 2 * Dd;
    for (int d = threadIdx.x; d < Dd; d += 256) {
        float v = xr[d] * inv * lnw[d];
        g_wi[(size_t)t * Dd + d] = v;
        __nv_bfloat16 hi = __float2bfloat16(v);
        __nv_bfloat16 lo = __float2bfloat16(v - __bfloat162float(hi));
        a1[d] = hi; a1[Dd + d] = lo;
    }
}

// ---------------- weight splits [hi|lo] ----------------
__global__ __launch_bounds__(256) void k_splitB1(const float* __restrict__ Wi) {
    int r = blockIdx.x;
    __nv_bfloat16* b1 = g_B1 + (size_t)r * 2 * Dd;
    const float* wr = Wi + (size_t)r * Dd;
    for (int d = threadIdx.x; d < Dd; d += 256) {
        float v = wr[d];
        __nv_bfloat16 hi = __float2bfloat16(v);
        __nv_bfloat16 lo = __float2bfloat16(v - __bfloat162float(hi));
        b1[d] = hi; b1[Dd + d] = lo;
    }
}
__global__ __launch_bounds__(256) void k_splitB2(const float* __restrict__ Wo) {
    int r = blockIdx.x;
    __nv_bfloat16* b2 = g_B2 + (size_t)r * 2 * Ff;
    const float* wr = Wo + (size_t)r * Ff;
    for (int d = threadIdx.x; d < Ff; d += 256) {
        float v = wr[d];
        __nv_bfloat16 hi = __float2bfloat16(v);
        __nv_bfloat16 lo = __float2bfloat16(v - __bfloat162float(hi));
        b2[d] = hi; b2[Ff + d] = lo;
    }
}

// ---------------- logits = wi_in @ Wg^T (float4 smem, conflict-free) ----------------
__global__ __launch_bounds__(256) void k_logits(const float* __restrict__ Wg,
                                                float* __restrict__ out) {
    __shared__ float4 sWg[(Dd / 4) * 16];   // [d4][e]
    for (int i = threadIdx.x; i < Dd * 16 / 4; i += 256) {
        int d4 = i / 16, e = i % 16;
        const float* w = Wg + (size_t)e * Dd + d4 * 4;
        sWg[d4 * 16 + e] = make_float4(w[0], w[1], w[2], w[3]);
    }
    __syncthreads();
    int tok = blockIdx.x * 16 + (threadIdx.x >> 4);
    int e = threadIdx.x & 15;
    const float4* wr = (const float4*)(g_wi + (size_t)tok * Dd);
    float s = 0.f;
    #pragma unroll 4
    for (int d4 = 0; d4 < Dd / 4; d4++) {
        float4 xv = wr[d4];
        float4 wv = sWg[d4 * 16 + e];
        s += xv.x * wv.x + xv.y * wv.y + xv.z * wv.z + xv.w * wv.w;
    }
    out[OFF_LOGITS + (size_t)tok * 16 + e] = s;
}

// ---------------- softmax / top2 / gates / aux partials ----------------
__global__ __launch_bounds__(256) void k_gate(const float* __restrict__ rp,
                                              float* __restrict__ out) {
    int t = blockIdx.x * 256 + threadIdx.x;
    int lane = threadIdx.x & 31;
    const float* lg = out + OFF_LOGITS + (size_t)t * 16;
    float l[16];
    float mx = -1e30f;
    #pragma unroll
    for (int e = 0; e < 16; e++) { l[e] = lg[e]; mx = fmaxf(mx, l[e]); }
    float se = 0.f;
    #pragma unroll
    for (int e = 0; e < 16; e++) se += __expf(l[e] - mx);
    float lse = mx + __logf(se);
    out[OFF_ENERGY + t] = -lse;

    int e0 = 0; float b0 = l[0];
    #pragma unroll
    for (int e = 1; e < 16; e++) if (l[e] > b0) { b0 = l[e]; e0 = e; }
    int e1 = -1; float b1 = -1e30f;
    #pragma unroll
    for (int e = 0; e < 16; e++) if (e != e0 && l[e] > b1) { b1 = l[e]; e1 = e; }
    float v0 = __expf(b0 - lse), v1 = __expf(b1 - lse);
    float den = v0 + v1; if (den < 1e-9f) den = 1e-9f;
    float G0 = v0 / den, G1 = v1 / den;
    g_e[t] = e0; g_e[Tn + t] = e1;
    g_gate[t] = G0; g_gate[Tn + t] = G1;
    g_sh1[t] = (rp[Tn + t] < G1 * 5.0f) ? 1 : 0;

    // warp-shuffle reductions for aux (b constant per block: 256 | 2048)
    int b = t >> 11;
    float zv = lse * lse;
    #pragma unroll
    for (int o = 16; o > 0; o >>= 1) zv += __shfl_xor_sync(0xffffffffu, zv, o);
    if (lane == 0) atomicAdd(&g_zl, zv);
    #pragma unroll
    for (int e = 0; e < 16; e++) {
        float pv = __expf(l[e] - lse);
        #pragma unroll
        for (int o = 16; o > 0; o >>= 1) pv += __shfl_xor_sync(0xffffffffu, pv, o);
        if (lane == 0) atomicAdd(&g_dp[b * 16 + e], pv);
    }
}

// ---------------- capacity scan + k-partitioned alive-list build ----------------
__global__ void k_scan(float* __restrict__ out) {
    if (threadIdx.x != 0) return;
    int b = blockIdx.x;
    int base = b * Nseq;
    int c0[16], cl[16];
    #pragma unroll
    for (int e = 0; e < 16; e++) { c0[e] = 0; cl[e] = 0; }
    for (int n = 0; n < Nseq; n++) {
        int t = base + n;
        int e = g_e[t];
        int pos = c0[e]++;
        bool s = pos < CAPc;
        g_gp[t] = s ? g_gate[t] : 0.f;
        out[OFF_GIDX + t] = s ? (float)e : 0.f;
        if (s) {
            int li = (b * 16 + e) * LCAP + cl[e];
            g_ltok[li] = t; g_lg[li] = g_gate[t];
            cl[e]++;
        }
    }
    int c1[16];
    #pragma unroll
    for (int e = 0; e < 16; e++) {
        int sv = c0[e] < CAPc ? c0[e] : CAPc;
        g_d1[b * 16 + e] = (float)sv / (float)Nseq;
        g_lcnt0[b * 16 + e] = cl[e];
        c1[e] = sv;
    }
    for (int n = 0; n < Nseq; n++) {
        int t = base + n;
        if (g_sh1[t]) {
            int e = g_e[Tn + t];
            int pos = c1[e]++;
            bool s = pos < CAPc;
            g_gp[Tn + t] = s ? g_gate[Tn + t] : 0.f;
            out[OFF_GIDX + Tn + t] = s ? (float)e : 0.f;
            if (s) {
                int li = (b * 16 + e) * LCAP + cl[e];
                g_ltok[li] = t; g_lg[li] = g_gate[Tn + t];
                cl[e]++;
            }
        } else {
            g_gp[Tn + t] = 0.f;
            out[OFF_GIDX + Tn + t] = 0.f;
        }
    }
    #pragma unroll
    for (int e = 0; e < 16; e++) g_lcnt[b * 16 + e] = cl[e];
}

// ---------------- aux scalars ----------------
__global__ void k_aux(float* __restrict__ out) {
    __shared__ float red[128];
    int i = threadIdx.x;
    red[i] = (g_dp[i] / (float)Nseq) * g_d1[i];
    __syncthreads();
    for (int o = 64; o > 0; o >>= 1) {
        if (i < o) red[i] += red[i + o];
        __syncthreads();
    }
    if (i == 0) {
        float bal = red[0] * 2.0f;
        float zl = g_zl / (float)Tn;
        out[OFF_BAL] = bal;
        out[OFF_ZL] = zl;
        out[OFF_AUX] = 0.01f * bal + 0.01f * zl;
    }
}

// ---------------- u1 = wi[t] @ Ai[e] per list entry (expert-grouped, no atomics) ----
__global__ __launch_bounds__(256) void k_u1g(const float* __restrict__ Ai) {
    extern __shared__ float buf[];          // Dd x 16
    int bi = blockIdx.x;
    int e = bi & 15;
    int cnt = g_lcnt[bi];
    int tid = threadIdx.x, lane = tid & 31, wid = tid >> 5;
    for (int i = tid; i < Dd * 16; i += 256) buf[i] = Ai[(size_t)e * Dd * 16 + i];
    __syncthreads();
    for (int i = wid; i < cnt; i += 8) {
        int t = g_ltok[bi * LCAP + i];
        int r = lane & 15, half = lane >> 4;
        const float* wr = g_wi + (size_t)t * Dd + half * 384;
        float acc = 0.f;
        #pragma unroll 4
        for (int d = 0; d < 384; d += 4) {
            float4 v = *(const float4*)(wr + d);
            int db = (half * 384 + d) * 16 + r;
            acc += v.x * buf[db] + v.y * buf[db + 16] + v.z * buf[db + 32] + v.w * buf[db + 48];
        }
        acc += __shfl_xor_sync(0xffffffffu, acc, 16);
        if (half == 0) g_u1[(bi * LCAP + i) * 16 + r] = acc;
    }
}

// ---------------- u2 = h[t] @ Ao[e] per list entry (grid.y=2 for parallelism) ------
__global__ __launch_bounds__(256) void k_u2g(const float* __restrict__ Ao) {
    extern __shared__ float buf[];          // Ff x 16
    int bi = blockIdx.x;
    int e = bi & 15;
    int cnt = g_lcnt[bi];
    int sub = blockIdx.y;
    int tid = threadIdx.x, lane = tid & 31, wid = tid >> 5;
    for (int i = tid; i < Ff * 16; i += 256) buf[i] = Ao[(size_t)e * Ff * 16 + i];
    __syncthreads();
    for (int i = wid + 8 * sub; i < cnt; i += 16) {
        int t = g_ltok[bi * LCAP + i];
        int r = lane & 15, half = lane >> 4;
        const float* hr = g_h + (size_t)t * Ff + half * 1536;
        float acc = 0.f;
        #pragma unroll 4
        for (int d = 0; d < 1536; d += 4) {
            float4 v = *(const float4*)(hr + d);
            int db = (half * 1536 + d) * 16 + r;
            acc += v.x * buf[db] + v.y * buf[db + 16] + v.z * buf[db + 32] + v.w * buf[db + 48];
        }
        acc += __shfl_xor_sync(0xffffffffu, acc, 16);
        if (half == 0) g_u2[(bi * LCAP + i) * 16 + r] = acc;
    }
}

// ---------------- h += 2g * (u1 @ Bi[e]), exclusive RMW per k-partition -----------
__global__ __launch_bounds__(256) void k_dh(const float* __restrict__ Bi, int which) {
    extern __shared__ float buf[];          // 16 x Ff
    int bi = blockIdx.x;
    int e = bi & 15;
    int cnt0 = g_lcnt0[bi], cnt = g_lcnt[bi];
    int start = which ? cnt0 : 0;
    int end   = which ? cnt  : cnt0;
    int tid = threadIdx.x, lane = tid & 31, wid = tid >> 5;
    for (int i = tid; i < 16 * Ff; i += 256) buf[i] = Bi[(size_t)e * 16 * Ff + i];
    __syncthreads();
    for (int i = start + wid; i < end; i += 8) {
        int t = g_ltok[bi * LCAP + i];
        float g2 = 2.f * g_lg[bi * LCAP + i];
        float ur = g_u1[(bi * LCAP + i) * 16 + (lane & 15)];
        float u[16];
        #pragma unroll
        for (int r = 0; r < 16; r++) u[r] = __shfl_sync(0xffffffffu, ur, r);
        float* hr = g_h + (size_t)t * Ff;
        for (int f = lane * 4; f < Ff; f += 128) {
            float4 hv = *(float4*)(hr + f);
            float dx = 0.f, dy = 0.f, dz = 0.f, dw = 0.f;
            #pragma unroll
            for (int r = 0; r < 16; r++) {
                float4 bv = *(const float4*)(buf + r * Ff + f);
                dx += u[r] * bv.x; dy += u[r] * bv.y; dz += u[r] * bv.z; dw += u[r] * bv.w;
            }
            hv.x += g2 * dx; hv.y += g2 * dy; hv.z += g2 * dz; hv.w += g2 * dw;
            *(float4*)(hr + f) = hv;
        }
    }
}

// ---------------- out += 2g * (u2 @ Bo[e]), exclusive RMW per k-partition ---------
__global__ __launch_bounds__(256) void k_dout(const float* __restrict__ Bo,
                                              float* __restrict__ out, int which) {
    extern __shared__ float buf[];          // 16 x Dd
    int bi = blockIdx.x;
    int e = bi & 15;
    int cnt0 = g_lcnt0[bi], cnt = g_lcnt[bi];
    int start = which ? cnt0 : 0;
    int end   = which ? cnt  : cnt0;
    int tid = threadIdx.x, lane = tid & 31, wid = tid >> 5;
    for (int i = tid; i < 16 * Dd; i += 256) buf[i] = Bo[(size_t)e * 16 * Dd + i];
    __syncthreads();
    for (int i = start + wid; i < end; i += 8) {
        int t = g_ltok[bi * LCAP + i];
        float g2 = 2.f * g_lg[bi * LCAP + i];
        float ur = g_u2[(bi * LCAP + i) * 16 + (lane & 15)];
        float u[16];
        #pragma unroll
        for (int r = 0; r < 16; r++) u[r] = __shfl_sync(0xffffffffu, ur, r);
        float* orow = out + (size_t)t * Dd;
        for (int f = lane * 4; f < Dd; f += 128) {
            float4 ov = *(float4*)(orow + f);
            float dx = 0.f, dy = 0.f, dz = 0.f, dw = 0.f;
            #pragma unroll
            for (int r = 0; r < 16; r++) {
                float4 bv = *(const float4*)(buf + r * Dd + f);
                dx += u[r] * bv.x; dy += u[r] * bv.y; dz += u[r] * bv.z; dw += u[r] * bv.w;
            }
            ov.x += g2 * dx; ov.y += g2 * dy; ov.z += g2 * dz; ov.w += g2 * dw;
            *(float4*)(orow + f) = ov;
        }
    }
}

// ---------------- A2 build from final h ([hi|lo]) ----------------
__global__ __launch_bounds__(256) void k_hC() {
    int t = blockIdx.x;
    const float* hr = g_h + (size_t)t * Ff;
    __nv_bfloat16* a2 = g_A2 + (size_t)t * 2 * Ff;
    for (int f = threadIdx.x; f < Ff; f += 256) {
        float v = hr[f];
        __nv_bfloat16 hi = __float2bfloat16(v);
        __nv_bfloat16 lo = __float2bfloat16(v - __bfloat162float(hi));
        a2[f] = hi; a2[Ff + f] = lo;
    }
}

// ---------------- launch ----------------
extern "C" void kernel_launch(void* const* d_in, const int* in_sizes, int n_in,
                              void* d_out, int out_size) {
    const float* x   = (const float*)d_in[0];
    const float* rp  = (const float*)d_in[1];
    const float* lnw = (const float*)d_in[2];
    const float* Wg  = (const float*)d_in[3];
    const float* Wi  = (const float*)d_in[4];
    const float* Wo  = (const float*)d_in[5];
    const float* Ai  = (const float*)d_in[6];
    const float* Bi  = (const float*)d_in[7];
    const float* Ao  = (const float*)d_in[8];
    const float* Bo  = (const float*)d_in[9];
    float* out = (float*)d_out;

    cudaFuncSetAttribute(k_tc_gemm, cudaFuncAttributeMaxDynamicSharedMemorySize, SMEM_GEMM);
    cudaFuncSetAttribute(k_u1g, cudaFuncAttributeMaxDynamicSharedMemorySize, SMEM_SML);
    cudaFuncSetAttribute(k_u2g, cudaFuncAttributeMaxDynamicSharedMemorySize, SMEM_BIG);
    cudaFuncSetAttribute(k_dh,  cudaFuncAttributeMaxDynamicSharedMemorySize, SMEM_BIG);
    cudaFuncSetAttribute(k_dout, cudaFuncAttributeMaxDynamicSharedMemorySize, SMEM_SML);

    __nv_bfloat16 *A1p, *B1p, *A2p, *B2p;
    float *hp;
    cudaGetSymbolAddress((void**)&A1p, g_A1);
    cudaGetSymbolAddress((void**)&B1p, g_B1);
    cudaGetSymbolAddress((void**)&A2p, g_A2);
    cudaGetSymbolAddress((void**)&B2p, g_B2);
    cudaGetSymbolAddress((void**)&hp, g_h);

    k_init<<<1, 128>>>();
    k_rms<<<Tn, 256>>>(x, lnw);
    k_splitB1<<<Ff, 256>>>(Wi);
    k_splitB2<<<Dd, 256>>>(Wo);
    k_logits<<<Tn / 16, 256>>>(Wg, out);
    k_gate<<<Tn / 256, 256>>>(rp, out);
    k_scan<<<Bbat, 32>>>(out);
    k_aux<<<1, 128>>>(out);
    k_u1g<<<Bbat * Ee, 256, SMEM_SML>>>(Ai);

    // GEMM1: h = relu(z) + gs*z   [16384 x 3072], K=768 (3-term schedule, 36 chunks)
    k_tc_gemm<<<dim3(Ff / 256, Tn / 128), 512, SMEM_GEMM>>>(A1p, B1p, hp, Ff, Dd, Dd / 64, 3 * Dd / 64, 1, nullptr);
    k_dh<<<Bbat * Ee, 256, SMEM_BIG>>>(Bi, 0);
    k_dh<<<Bbat * Ee, 256, SMEM_BIG>>>(Bi, 1);
    k_hC<<<Tn, 256>>>();
    k_u2g<<<dim3(Bbat * Ee, 2), 256, SMEM_BIG>>>(Ao);

    // GEMM2: out = x + (1+gs)*(h @ Wo^T)   [16384 x 768], K=3072 (144 chunks)
    k_tc_gemm<<<dim3(Dd / 256, Tn / 128), 512, SMEM_GEMM>>>(A2p, B2p, out, Dd, Ff, Ff / 64, 3 * Ff / 64, 2, x);
    k_dout<<<Bbat * Ee, 256, SMEM_SML>>>(Bo, out, 0);
    k_dout<<<Bbat * Ee, 256, SMEM_SML>>>(Bo, out, 1);
}

// round 8
// speedup vs baseline: 1.3791x; 1.3791x over previous
#include <cuda_runtime.h>
#include <cuda_bf16.h>
#include <math.h>
#include <stdint.h>

// Problem constants
#define Tn 16384            // B*N tokens
#define Dd 768
#define Ff 3072
#define Ee 16
#define CAPc 160
#define Bbat 8
#define Nseq 2048

// Output layout (float32, concatenated in reference return order)
#define OFF_AUX    12582912
#define OFF_BAL    12582913
#define OFF_ZL     12582914
#define OFF_LOGITS 12582915ll
#define OFF_ENERGY 12845059ll
#define OFF_GIDX   12861443ll

// ---------------- scratch (device globals; no runtime allocation) ----------------
__device__ float g_wi[(size_t)Tn * Dd];               // RMS-normed input (fp32)
__device__ float g_h [(size_t)Tn * Ff];               // z, then h in-place (fp32)
__device__ float g_w [(size_t)Tn * Dd];               // h @ Wo^T (raw)
__device__ __nv_bfloat16 g_A1[(size_t)Tn * 2 * Dd];   // [wi_hi | wi_lo]
__device__ __nv_bfloat16 g_B1[(size_t)Ff * 2 * Dd];   // [Wi_hi | Wi_lo]
__device__ __nv_bfloat16 g_A2[(size_t)Tn * 2 * Ff];   // [h_hi  | h_lo]
__device__ __nv_bfloat16 g_B2[(size_t)Dd * 2 * Ff];   // [Wo_hi | Wo_lo]
__device__ float g_u1[2 * Tn * 16];
__device__ float g_u2[2 * Tn * 16];
__device__ int   g_e  [2 * Tn];
__device__ float g_gate[2 * Tn];
__device__ float g_gp  [2 * Tn];                      // gate after drop (0 if dropped)
__device__ int   g_sh1 [Tn];
__device__ float g_dp[Bbat * Ee];
__device__ float g_d1[Bbat * Ee];
__device__ float g_zl;

// ---------------- PTX helpers (sm_100-safe) ----------------
__device__ __forceinline__ uint32_t s2u(const void* p) {
    uint32_t a;
    asm("{ .reg .u64 t; cvta.to.shared.u64 t, %1; cvt.u32.u64 %0, t; }" : "=r"(a) : "l"(p));
    return a;
}
__device__ __forceinline__ void cpa16(uint32_t s, const void* g) {
    asm volatile("cp.async.cg.shared.global [%0], [%1], 16;\n" :: "r"(s), "l"(g));
}
#define CPA_COMMIT() asm volatile("cp.async.commit_group;\n" ::: "memory")
#define CPA_WAIT1()  asm volatile("cp.async.wait_group 1;\n" ::: "memory")

__device__ __forceinline__ void ldsm4(uint32_t* r, uint32_t a) {
    asm volatile("ldmatrix.sync.aligned.m8n8.x4.shared.b16 {%0,%1,%2,%3}, [%4];"
                 : "=r"(r[0]), "=r"(r[1]), "=r"(r[2]), "=r"(r[3]) : "r"(a));
}
__device__ __forceinline__ void mma16816(float* c, const uint32_t* a, uint32_t b0, uint32_t b1) {
    asm volatile("mma.sync.aligned.m16n8k16.row.col.f32.bf16.bf16.f32 "
                 "{%0,%1,%2,%3}, {%4,%5,%6,%7}, {%8,%9}, {%0,%1,%2,%3};"
                 : "+f"(c[0]), "+f"(c[1]), "+f"(c[2]), "+f"(c[3])
                 : "r"(a[0]), "r"(a[1]), "r"(a[2]), "r"(a[3]), "r"(b0), "r"(b1));
}

#define SWZ(o) ((o) ^ (((o) >> 3) & 0x70))

// GEMM smem: A stages [128][64]bf16 = 16KB (x3), B stages [128][64]bf16 = 16KB (x3)
#define SM_A(s) ((s) * 16384)
#define SM_B(s) (49152 + (s) * 16384)
#define SMEM_GEMM 98304

// ---------------- stage loader: chunk c of the 3-term schedule over 2-term storage ----
// A terms: hi, lo, hi ; B terms: hi, hi, lo
__device__ __forceinline__ void load_stage(uint32_t sb, int s,
                                           const __nv_bfloat16* __restrict__ A,
                                           const __nv_bfloat16* __restrict__ B,
                                           int bm, int bn, int c, int cpt, int K, int tid) {
    int t = c / cpt;
    int kc = (c - t * cpt) * 64;
    int aoff = (t == 1) ? K : 0;
    int boff = (t == 2) ? K : 0;
    const int K2 = 2 * K;
    #pragma unroll
    for (int j = 0; j < 4; j++) {
        int idx = tid + 256 * j, row = idx >> 3, seg = idx & 7;
        cpa16(sb + SM_A(s) + SWZ(row * 128 + seg * 16),
              A + (size_t)(bm + row) * K2 + aoff + kc + seg * 8);
    }
    #pragma unroll
    for (int j = 0; j < 4; j++) {
        int idx = tid + 256 * j, row = idx >> 3, seg = idx & 7;
        cpa16(sb + SM_B(s) + SWZ(row * 128 + seg * 16),
              B + (size_t)(bn + row) * K2 + boff + kc + seg * 8);
    }
}

// ---------------- mma.sync split-bf16 GEMM (raw store): C[m,n] = sum_k A[m,k]*B[n,k] ----
// Tile 128(M) x 128(N), K-chunk 64, 3-stage cp.async pipeline, 256 threads, 2 CTAs/SM.
__global__ __launch_bounds__(256, 2)
void k_tc_gemm(const __nv_bfloat16* __restrict__ A, const __nv_bfloat16* __restrict__ B,
               float* __restrict__ C, int Ncols, int K, int cpt, int KI) {
    extern __shared__ char smem[];
    const uint32_t sb = s2u(smem);
    const int tid = threadIdx.x;
    const int wid = tid >> 5;
    const int lane = tid & 31;
    const int warp_m = wid & 1;          // 2 groups of M=64
    const int warp_n = wid >> 1;         // 4 groups of N=32
    const int bm = blockIdx.y * 128;
    const int bn = blockIdx.x * 128;

    float acc[4][4][4];
    #pragma unroll
    for (int i = 0; i < 4; i++)
        #pragma unroll
        for (int j = 0; j < 4; j++)
            #pragma unroll
            for (int q = 0; q < 4; q++) acc[i][j][q] = 0.f;

    // prologue: stages 0,1
    #pragma unroll
    for (int c = 0; c < 2; c++) {
        load_stage(sb, c, A, B, bm, bn, c, cpt, K, tid);
        CPA_COMMIT();
    }

    for (int i = 0; i < KI; i++) {
        const int si = i % 3;
        CPA_WAIT1();
        __syncthreads();

        const int j = i + 2;
        if (j < KI) load_stage(sb, j % 3, A, B, bm, bn, j, cpt, K, tid);
        CPA_COMMIT();

        const uint32_t sa = sb + SM_A(si);
        const uint32_t sB = sb + SM_B(si);
        #pragma unroll
        for (int ks = 0; ks < 4; ks++) {
            uint32_t a[4][4];
            #pragma unroll
            for (int mt = 0; mt < 4; mt++) {
                int row = warp_m * 64 + mt * 16 + (lane & 15);
                ldsm4(a[mt], sa + SWZ(row * 128 + ks * 32 + ((lane >> 4) << 4)));
            }
            uint32_t b[2][4];
            #pragma unroll
            for (int g = 0; g < 2; g++) {
                int nr = warp_n * 32 + g * 16 + ((lane >> 4) << 3) + (lane & 7);
                ldsm4(b[g], sB + SWZ(nr * 128 + ks * 32 + (((lane >> 3) & 1) << 4)));
            }
            #pragma unroll
            for (int mt = 0; mt < 4; mt++)
                #pragma unroll
                for (int nt = 0; nt < 4; nt++) {
                    int g = nt >> 1, hf = (nt & 1) << 1;
                    mma16816(acc[mt][nt], a[mt], b[g][hf], b[g][hf + 1]);
                }
        }
        __syncthreads();
    }

    // raw fp32 store
    #pragma unroll
    for (int mt = 0; mt < 4; mt++) {
        int r0 = bm + warp_m * 64 + mt * 16 + (lane >> 2);
        #pragma unroll
        for (int nt = 0; nt < 4; nt++) {
            int col = bn + warp_n * 32 + nt * 8 + (lane & 3) * 2;
            *(float2*)(C + (size_t)r0 * Ncols + col)       = make_float2(acc[mt][nt][0], acc[mt][nt][1]);
            *(float2*)(C + (size_t)(r0 + 8) * Ncols + col) = make_float2(acc[mt][nt][2], acc[mt][nt][3]);
        }
    }
}

// ---------------- RMS norm (+ split-bf16 A1 build + accumulator init fold) ------------
__global__ __launch_bounds__(256) void k_rms(const float* __restrict__ x,
                                             const float* __restrict__ lnw) {
    if (blockIdx.x == 0) {
        if (threadIdx.x < Bbat * Ee) g_dp[threadIdx.x] = 0.f;
        if (threadIdx.x == 0) g_zl = 0.f;
    }
    int t = blockIdx.x;
    const float* xr = x + (size_t)t * Dd;
    float s = 0.f;
    for (int d = threadIdx.x; d < Dd; d += 256) { float v = xr[d]; s += v * v; }
    __shared__ float red[256];
    red[threadIdx.x] = s; __syncthreads();
    for (int o = 128; o > 0; o >>= 1) {
        if (threadIdx.x < o) red[threadIdx.x] += red[threadIdx.x + o];
        __syncthreads();
    }
    float inv = rsqrtf(red[0] / (float)Dd + 1e-6f);
    __nv_bfloat16* a1 = g_A1 + (size_t)t * 2 * Dd;
    for (int d = threadIdx.x; d < Dd; d += 256) {
        float v = xr[d] * inv * lnw[d];
        g_wi[(size_t)t * Dd + d] = v;
        __nv_bfloat16 hi = __float2bfloat16(v);
        __nv_bfloat16 lo = __float2bfloat16(v - __bfloat162float(hi));
        a1[d] = hi; a1[Dd + d] = lo;
    }
}

// ---------------- weight splits [hi|lo] ----------------
__global__ __launch_bounds__(256) void k_splitB1(const float* __restrict__ Wi) {
    int r = blockIdx.x;
    __nv_bfloat16* b1 = g_B1 + (size_t)r * 2 * Dd;
    const float* wr = Wi + (size_t)r * Dd;
    for (int d = threadIdx.x; d < Dd; d += 256) {
        float v = wr[d];
        __nv_bfloat16 hi = __float2bfloat16(v);
        __nv_bfloat16 lo = __float2bfloat16(v - __bfloat162float(hi));
        b1[d] = hi; b1[Dd + d] = lo;
    }
}
__global__ __launch_bounds__(256) void k_splitB2(const float* __restrict__ Wo) {
    int r = blockIdx.x;
    __nv_bfloat16* b2 = g_B2 + (size_t)r * 2 * Ff;
    const float* wr = Wo + (size_t)r * Ff;
    for (int d = threadIdx.x; d < Ff; d += 256) {
        float v = wr[d];
        __nv_bfloat16 hi = __float2bfloat16(v);
        __nv_bfloat16 lo = __float2bfloat16(v - __bfloat162float(hi));
        b2[d] = hi; b2[Ff + d] = lo;
    }
}

// ---------------- logits = wi_in @ Wg^T (float4 smem) ----------------
__global__ __launch_bounds__(256) void k_logits(const float* __restrict__ Wg,
                                                float* __restrict__ out) {
    __shared__ float4 sWg[(Dd / 4) * 16];   // [d4][e]
    for (int i = threadIdx.x; i < Dd * 16 / 4; i += 256) {
        int d4 = i / 16, e = i % 16;
        const float* w = Wg + (size_t)e * Dd + d4 * 4;
        sWg[d4 * 16 + e] = make_float4(w[0], w[1], w[2], w[3]);
    }
    __syncthreads();
    int tok = blockIdx.x * 16 + (threadIdx.x >> 4);
    int e = threadIdx.x & 15;
    const float4* wr = (const float4*)(g_wi + (size_t)tok * Dd);
    float s = 0.f;
    #pragma unroll 4
    for (int d4 = 0; d4 < Dd / 4; d4++) {
        float4 xv = wr[d4];
        float4 wv = sWg[d4 * 16 + e];
        s += xv.x * wv.x + xv.y * wv.y + xv.z * wv.z + xv.w * wv.w;
    }
    out[OFF_LOGITS + (size_t)tok * 16 + e] = s;
}

// ---------------- softmax / top2 / gates / aux partials ----------------
__global__ __launch_bounds__(256) void k_gate(const float* __restrict__ rp,
                                              float* __restrict__ out) {
    int t = blockIdx.x * 256 + threadIdx.x;
    int lane = threadIdx.x & 31;
    const float* lg = out + OFF_LOGITS + (size_t)t * 16;
    float l[16];
    float mx = -1e30f;
    #pragma unroll
    for (int e = 0; e < 16; e++) { l[e] = lg[e]; mx = fmaxf(mx, l[e]); }
    float se = 0.f;
    #pragma unroll
    for (int e = 0; e < 16; e++) se += __expf(l[e] - mx);
    float lse = mx + __logf(se);
    out[OFF_ENERGY + t] = -lse;

    int e0 = 0; float b0 = l[0];
    #pragma unroll
    for (int e = 1; e < 16; e++) if (l[e] > b0) { b0 = l[e]; e0 = e; }
    int e1 = -1; float b1 = -1e30f;
    #pragma unroll
    for (int e = 0; e < 16; e++) if (e != e0 && l[e] > b1) { b1 = l[e]; e1 = e; }
    float v0 = __expf(b0 - lse), v1 = __expf(b1 - lse);
    float den = v0 + v1; if (den < 1e-9f) den = 1e-9f;
    float G0 = v0 / den, G1 = v1 / den;
    g_e[t] = e0; g_e[Tn + t] = e1;
    g_gate[t] = G0; g_gate[Tn + t] = G1;
    g_sh1[t] = (rp[Tn + t] < G1 * 5.0f) ? 1 : 0;

    int b = t >> 11;
    float zv = lse * lse;
    #pragma unroll
    for (int o = 16; o > 0; o >>= 1) zv += __shfl_xor_sync(0xffffffffu, zv, o);
    if (lane == 0) atomicAdd(&g_zl, zv);
    #pragma unroll
    for (int e = 0; e < 16; e++) {
        float pv = __expf(l[e] - lse);
        #pragma unroll
        for (int o = 16; o > 0; o >>= 1) pv += __shfl_xor_sync(0xffffffffu, pv, o);
        if (lane == 0) atomicAdd(&g_dp[b * 16 + e], pv);
    }
}

// ---------------- capacity scan ----------------
__global__ void k_scan(float* __restrict__ out) {
    if (threadIdx.x != 0) return;
    int b = blockIdx.x;
    int base = b * Nseq;
    int c0[16];
    #pragma unroll
    for (int e = 0; e < 16; e++) c0[e] = 0;
    for (int n = 0; n < Nseq; n++) {
        int t = base + n;
        int e = g_e[t];
        int pos = c0[e]++;
        bool s = pos < CAPc;
        g_gp[t] = s ? g_gate[t] : 0.f;
        out[OFF_GIDX + t] = s ? (float)e : 0.f;
    }
    int c1[16];
    #pragma unroll
    for (int e = 0; e < 16; e++) {
        int sv = c0[e] < CAPc ? c0[e] : CAPc;
        g_d1[b * 16 + e] = (float)sv / (float)Nseq;
        c1[e] = sv;
    }
    for (int n = 0; n < Nseq; n++) {
        int t = base + n;
        if (g_sh1[t]) {
            int e = g_e[Tn + t];
            int pos = c1[e]++;
            bool s = pos < CAPc;
            g_gp[Tn + t] = s ? g_gate[Tn + t] : 0.f;
            out[OFF_GIDX + Tn + t] = s ? (float)e : 0.f;
        } else {
            g_gp[Tn + t] = 0.f;
            out[OFF_GIDX + Tn + t] = 0.f;
        }
    }
}

// ---------------- aux scalars ----------------
__global__ void k_aux(float* __restrict__ out) {
    __shared__ float red[128];
    int i = threadIdx.x;
    red[i] = (g_dp[i] / (float)Nseq) * g_d1[i];
    __syncthreads();
    for (int o = 64; o > 0; o >>= 1) {
        if (i < o) red[i] += red[i + o];
        __syncthreads();
    }
    if (i == 0) {
        float bal = red[0] * 2.0f;
        float zl = g_zl / (float)Tn;
        out[OFF_BAL] = bal;
        out[OFF_ZL] = zl;
        out[OFF_AUX] = 0.01f * bal + 0.01f * zl;
    }
}

// ---------------- LoRA u vectors (per-token, R4-proven) ----------------
__global__ __launch_bounds__(128) void k_u1(const float* __restrict__ Ai) {
    int t = blockIdx.x, k = blockIdx.y;
    int idx = k * Tn + t;
    float gp = g_gp[idx];
    if (gp == 0.f) {
        if (threadIdx.x < 16) g_u1[idx * 16 + threadIdx.x] = 0.f;
        return;
    }
    int e = g_e[idx];
    int r = threadIdx.x & 15, seg = threadIdx.x >> 4;
    const float* Ae = Ai + (size_t)e * Dd * 16;
    const float* wr = g_wi + (size_t)t * Dd;
    float acc = 0.f;
    int d0 = seg * 96;
    #pragma unroll 4
    for (int d = d0; d < d0 + 96; d++) acc += wr[d] * Ae[d * 16 + r];
    __shared__ float red[128];
    red[threadIdx.x] = acc; __syncthreads();
    if (threadIdx.x < 16) {
        float s = 0.f;
        #pragma unroll
        for (int j = 0; j < 8; j++) s += red[j * 16 + r];
        g_u1[idx * 16 + r] = s;
    }
}

__global__ __launch_bounds__(128) void k_u2(const float* __restrict__ Ao) {
    int t = blockIdx.x, k = blockIdx.y;
    int idx = k * Tn + t;
    float gp = g_gp[idx];
    if (gp == 0.f) {
        if (threadIdx.x < 16) g_u2[idx * 16 + threadIdx.x] = 0.f;
        return;
    }
    int e = g_e[idx];
    int r = threadIdx.x & 15, seg = threadIdx.x >> 4;
    const float* Ae = Ao + (size_t)e * Ff * 16;
    const float* hr = g_h + (size_t)t * Ff;
    float acc = 0.f;
    int d0 = seg * 384;
    #pragma unroll 4
    for (int d = d0; d < d0 + 384; d++) acc += hr[d] * Ae[d * 16 + r];
    __shared__ float red[128];
    red[threadIdx.x] = acc; __syncthreads();
    if (threadIdx.x < 16) {
        float s = 0.f;
        #pragma unroll
        for (int j = 0; j < 8; j++) s += red[j * 16 + r];
        g_u2[idx * 16 + r] = s;
    }
}

// ---------------- h = relu(z) + gs*z + 2*g_k*(u_k@Bi[e_k]), + A2 build ----------------
__global__ __launch_bounds__(256) void k_h(const float* __restrict__ Bi) {
    int t = blockIdx.x;
    float g0 = g_gp[t], g1 = g_gp[Tn + t];
    int e0 = g_e[t], e1 = g_e[Tn + t];
    __shared__ float su0[16], su1[16];
    if (threadIdx.x < 16) {
        su0[threadIdx.x] = g_u1[t * 16 + threadIdx.x];
        su1[threadIdx.x] = g_u1[(Tn + t) * 16 + threadIdx.x];
    }
    __syncthreads();
    float gs = g0 + g1;
    const float* B0 = Bi + (size_t)e0 * 16 * Ff;
    const float* B1 = Bi + (size_t)e1 * 16 * Ff;
    float* hr = g_h + (size_t)t * Ff;
    __nv_bfloat16* a2 = g_A2 + (size_t)t * 2 * Ff;
    for (int f = threadIdx.x; f < Ff; f += 256) {
        float z = hr[f];
        float acc = fmaxf(z, 0.f) + gs * z;
        if (g0 != 0.f) {
            float dsum = 0.f;
            #pragma unroll
            for (int r = 0; r < 16; r++) dsum += su0[r] * B0[r * Ff + f];
            acc += 2.f * g0 * dsum;
        }
        if (g1 != 0.f) {
            float dsum = 0.f;
            #pragma unroll
            for (int r = 0; r < 16; r++) dsum += su1[r] * B1[r * Ff + f];
            acc += 2.f * g1 * dsum;
        }
        hr[f] = acc;
        __nv_bfloat16 hi = __float2bfloat16(acc);
        __nv_bfloat16 lo = __float2bfloat16(acc - __bfloat162float(hi));
        a2[f] = hi; a2[Ff + f] = lo;
    }
}

// ---------------- out = x + (1+gs)*w + 2*g_k*(u2_k@Bo[e_k]) ----------------
__global__ __launch_bounds__(256) void k_final(const float* __restrict__ x,
                                               const float* __restrict__ Bo,
                                               float* __restrict__ out) {
    int t = blockIdx.x;
    float g0 = g_gp[t], g1 = g_gp[Tn + t];
    int e0 = g_e[t], e1 = g_e[Tn + t];
    __shared__ float su0[16], su1[16];
    if (threadIdx.x < 16) {
        su0[threadIdx.x] = g_u2[t * 16 + threadIdx.x];
        su1[threadIdx.x] = g_u2[(Tn + t) * 16 + threadIdx.x];
    }
    __syncthreads();
    float gs = g0 + g1;
    const float* B0 = Bo + (size_t)e0 * 16 * Dd;
    const float* B1 = Bo + (size_t)e1 * 16 * Dd;
    for (int d = threadIdx.x; d < Dd; d += 256) {
        float w = g_w[(size_t)t * Dd + d];
        float acc = x[(size_t)t * Dd + d] + w + gs * w;
        if (g0 != 0.f) {
            float dsum = 0.f;
            #pragma unroll
            for (int r = 0; r < 16; r++) dsum += su0[r] * B0[r * Dd + d];
            acc += 2.f * g0 * dsum;
        }
        if (g1 != 0.f) {
            float dsum = 0.f;
            #pragma unroll
            for (int r = 0; r < 16; r++) dsum += su1[r] * B1[r * Dd + d];
            acc += 2.f * g1 * dsum;
        }
        out[(size_t)t * Dd + d] = acc;
    }
}

// ---------------- launch ----------------
extern "C" void kernel_launch(void* const* d_in, const int* in_sizes, int n_in,
                              void* d_out, int out_size) {
    const float* x   = (const float*)d_in[0];
    const float* rp  = (const float*)d_in[1];
    const float* lnw = (const float*)d_in[2];
    const float* Wg  = (const float*)d_in[3];
    const float* Wi  = (const float*)d_in[4];
    const float* Wo  = (const float*)d_in[5];
    const float* Ai  = (const float*)d_in[6];
    const float* Bi  = (const float*)d_in[7];
    const float* Ao  = (const float*)d_in[8];
    const float* Bo  = (const float*)d_in[9];
    float* out = (float*)d_out;

    cudaFuncSetAttribute(k_tc_gemm, cudaFuncAttributeMaxDynamicSharedMemorySize, SMEM_GEMM);

    __nv_bfloat16 *A1p, *B1p, *A2p, *B2p;
    float *hp, *wp;
    cudaGetSymbolAddress((void**)&A1p, g_A1);
    cudaGetSymbolAddress((void**)&B1p, g_B1);
    cudaGetSymbolAddress((void**)&A2p, g_A2);
    cudaGetSymbolAddress((void**)&B2p, g_B2);
    cudaGetSymbolAddress((void**)&hp, g_h);
    cudaGetSymbolAddress((void**)&wp, g_w);

    // launch #1..#3: prep for GEMM1
    k_rms<<<Tn, 256>>>(x, lnw);                 // A1, g_wi (+init fold)
    k_splitB1<<<Ff, 256>>>(Wi);                 // B1
    k_splitB2<<<Dd, 256>>>(Wo);                 // B2
    // launch #4: GEMM1 raw (z -> g_h)  [ncu capture slot]
    k_tc_gemm<<<dim3(Ff / 128, Tn / 128), 256, SMEM_GEMM>>>(A1p, B1p, hp, Ff, Dd, Dd / 64, 3 * Dd / 64);
    // gating chain
    k_logits<<<Tn / 16, 256>>>(Wg, out);
    k_gate<<<Tn / 256, 256>>>(rp, out);
    k_scan<<<Bbat, 32>>>(out);
    k_aux<<<1, 128>>>(out);
    // wi-path LoRA + h epilogue + A2 build
    dim3 gu(Tn, 2);
    k_u1<<<gu, 128>>>(Ai);
    k_h<<<Tn, 256>>>(Bi);
    // wo-path
    k_u2<<<gu, 128>>>(Ao);
    k_tc_gemm<<<dim3(Dd / 128, Tn / 128), 256, SMEM_GEMM>>>(A2p, B2p, wp, Dd, Ff, Ff / 64, 3 * Ff / 64);
    k_final<<<Tn, 256>>>(x, Bo, out);
}

// round 11
// speedup vs baseline: 1.6229x; 1.1767x over previous
#include <cuda_runtime.h>
#include <cuda_bf16.h>
#include <math.h>
#include <stdint.h>

// Problem constants
#define Tn 16384            // B*N tokens
#define Dd 768
#define Ff 3072
#define Ee 16
#define CAPc 160
#define Bbat 8
#define Nseq 2048

#define N1X 3328            // GEMM1 N: 3072 z + 256 u1
#define N2X 1024            // GEMM2 N: 768 w + 256 u2
#define HXs 3328            // g_hx row stride
#define WXs 1024            // g_wx row stride

// Output layout (float32, concatenated in reference return order)
#define OFF_AUX    12582912
#define OFF_BAL    12582913
#define OFF_ZL     12582914
#define OFF_LOGITS 12582915ll
#define OFF_ENERGY 12845059ll
#define OFF_GIDX   12861443ll

// ---------------- scratch (device globals; no runtime allocation) ----------------
__device__ float g_wi[(size_t)Tn * Dd];                 // RMS-normed input (fp32)
__device__ float g_hx[(size_t)Tn * HXs];                // [z | u1_all] raw
__device__ float g_wx[(size_t)Tn * WXs];                // [w | u2_all] raw
__device__ __nv_bfloat16 g_A1 [(size_t)Tn * 2 * Dd];    // [wi_hi | wi_lo]
__device__ __nv_bfloat16 g_B1x[(size_t)N1X * 2 * Dd];   // [Wi|Ai rows, hi|lo]
__device__ __nv_bfloat16 g_A2 [(size_t)Tn * 2 * Ff];    // [h_hi | h_lo]
__device__ __nv_bfloat16 g_B2x[(size_t)N2X * 2 * Ff];   // [Wo|Ao rows, hi|lo]
__device__ __nv_bfloat16 g_V1 [(size_t)Tn * 512];       // gated u1 [hi|lo], K=256
__device__ __nv_bfloat16 g_V2 [(size_t)Tn * 512];       // gated u2 [hi|lo]
__device__ __nv_bfloat16 g_Bd1[(size_t)Ff * 512];       // Bi^T rows [hi|lo]
__device__ __nv_bfloat16 g_Bd2[(size_t)Dd * 512];       // Bo^T rows [hi|lo]
__device__ int   g_e  [2 * Tn];
__device__ float g_gate[2 * Tn];
__device__ float g_gp  [2 * Tn];                        // gate after drop (0 if dropped)
__device__ int   g_sh1 [Tn];
__device__ float g_dp[Bbat * Ee];
__device__ float g_d1[Bbat * Ee];
__device__ float g_zl;

// ---------------- PTX helpers (sm_100-safe) ----------------
__device__ __forceinline__ uint32_t s2u(const void* p) {
    uint32_t a;
    asm("{ .reg .u64 t; cvta.to.shared.u64 t, %1; cvt.u32.u64 %0, t; }" : "=r"(a) : "l"(p));
    return a;
}
__device__ __forceinline__ void cpa16(uint32_t s, const void* g) {
    asm volatile("cp.async.cg.shared.global [%0], [%1], 16;\n" :: "r"(s), "l"(g));
}
#define CPA_COMMIT() asm volatile("cp.async.commit_group;\n" ::: "memory")
#define CPA_WAIT1()  asm volatile("cp.async.wait_group 1;\n" ::: "memory")

__device__ __forceinline__ void ldsm4(uint32_t* r, uint32_t a) {
    asm volatile("ldmatrix.sync.aligned.m8n8.x4.shared.b16 {%0,%1,%2,%3}, [%4];"
                 : "=r"(r[0]), "=r"(r[1]), "=r"(r[2]), "=r"(r[3]) : "r"(a));
}
__device__ __forceinline__ void mma16816(float* c, const uint32_t* a, uint32_t b0, uint32_t b1) {
    asm volatile("mma.sync.aligned.m16n8k16.row.col.f32.bf16.bf16.f32 "
                 "{%0,%1,%2,%3}, {%4,%5,%6,%7}, {%8,%9}, {%0,%1,%2,%3};"
                 : "+f"(c[0]), "+f"(c[1]), "+f"(c[2]), "+f"(c[3])
                 : "r"(a[0]), "r"(a[1]), "r"(a[2]), "r"(a[3]), "r"(b0), "r"(b1));
}

#define SWZ(o) ((o) ^ (((o) >> 3) & 0x70))

// GEMM smem: A stages [128][64]bf16 = 16KB (x3), B stages [128][64]bf16 = 16KB (x3)
#define SM_A(s) ((s) * 16384)
#define SM_B(s) (49152 + (s) * 16384)
#define SMEM_GEMM 98304

__device__ __forceinline__ __nv_bfloat162 split_hi2(float a, float b,
                                                    __nv_bfloat162& lo) {
    __nv_bfloat162 hi;
    hi.x = __float2bfloat16(a); hi.y = __float2bfloat16(b);
    lo.x = __float2bfloat16(a - __bfloat162float(hi.x));
    lo.y = __float2bfloat16(b - __bfloat162float(hi.y));
    return hi;
}

// ---------------- stage loader: chunk c of the 3-term schedule over 2-term storage ----
// A terms: hi, lo, hi ; B terms: hi, hi, lo
__device__ __forceinline__ void load_stage(uint32_t sb, int s,
                                           const __nv_bfloat16* __restrict__ A,
                                           const __nv_bfloat16* __restrict__ B,
                                           int bm, int bn, int c, int cpt, int K, int tid) {
    int t = c / cpt;
    int kc = (c - t * cpt) * 64;
    int aoff = (t == 1) ? K : 0;
    int boff = (t == 2) ? K : 0;
    const int K2 = 2 * K;
    #pragma unroll
    for (int j = 0; j < 4; j++) {
        int idx = tid + 256 * j, row = idx >> 3, seg = idx & 7;
        cpa16(sb + SM_A(s) + SWZ(row * 128 + seg * 16),
              A + (size_t)(bm + row) * K2 + aoff + kc + seg * 8);
    }
    #pragma unroll
    for (int j = 0; j < 4; j++) {
        int idx = tid + 256 * j, row = idx >> 3, seg = idx & 7;
        cpa16(sb + SM_B(s) + SWZ(row * 128 + seg * 16),
              B + (size_t)(bn + row) * K2 + boff + kc + seg * 8);
    }
}

// ---------------- mma.sync split-bf16 GEMM: C[m,n] = sum_k A[m,k]*B[n,k] ----------------
// Tile 128x128, K-chunk 64, 3-stage cp.async, 256 threads, 2 CTAs/SM.
// mode 0: raw store to C (stride Ncols)
// mode 1: h-epilogue: z=aux1 (stride HXs); h=relu(z)+gs*z+acc; write A2 [hi|lo] (a2o)
// mode 2: out-epilogue: out = aux1(x,768) + (1+gs)*aux2(w,WXs) + acc; store C (768)
__global__ __launch_bounds__(256, 2)
void k_tc_gemm(const __nv_bfloat16* __restrict__ A, const __nv_bfloat16* __restrict__ B,
               float* __restrict__ C, int Ncols, int K, int cpt, int KI, int mode,
               const float* __restrict__ aux1, const float* __restrict__ aux2,
               __nv_bfloat16* __restrict__ a2o) {
    extern __shared__ char smem[];
    const uint32_t sb = s2u(smem);
    const int tid = threadIdx.x;
    const int wid = tid >> 5;
    const int lane = tid & 31;
    const int warp_m = wid & 1;          // 2 groups of M=64
    const int warp_n = wid >> 1;         // 4 groups of N=32
    const int bm = blockIdx.y * 128;
    const int bn = blockIdx.x * 128;

    float acc[4][4][4];
    #pragma unroll
    for (int i = 0; i < 4; i++)
        #pragma unroll
        for (int j = 0; j < 4; j++)
            #pragma unroll
            for (int q = 0; q < 4; q++) acc[i][j][q] = 0.f;

    #pragma unroll
    for (int c = 0; c < 2; c++) {
        load_stage(sb, c, A, B, bm, bn, c, cpt, K, tid);
        CPA_COMMIT();
    }

    for (int i = 0; i < KI; i++) {
        const int si = i % 3;
        CPA_WAIT1();
        __syncthreads();

        const int j = i + 2;
        if (j < KI) load_stage(sb, j % 3, A, B, bm, bn, j, cpt, K, tid);
        CPA_COMMIT();

        const uint32_t sa = sb + SM_A(si);
        const uint32_t sB = sb + SM_B(si);
        #pragma unroll
        for (int ks = 0; ks < 4; ks++) {
            uint32_t a[4][4];
            #pragma unroll
            for (int mt = 0; mt < 4; mt++) {
                int row = warp_m * 64 + mt * 16 + (lane & 15);
                ldsm4(a[mt], sa + SWZ(row * 128 + ks * 32 + ((lane >> 4) << 4)));
            }
            uint32_t b[2][4];
            #pragma unroll
            for (int g = 0; g < 2; g++) {
                int nr = warp_n * 32 + g * 16 + ((lane >> 4) << 3) + (lane & 7);
                ldsm4(b[g], sB + SWZ(nr * 128 + ks * 32 + (((lane >> 3) & 1) << 4)));
            }
            #pragma unroll
            for (int mt = 0; mt < 4; mt++)
                #pragma unroll
                for (int nt = 0; nt < 4; nt++) {
                    int g = nt >> 1, hf = (nt & 1) << 1;
                    mma16816(acc[mt][nt], a[mt], b[g][hf], b[g][hf + 1]);
                }
        }
        __syncthreads();
    }

    if (mode == 0) {
        #pragma unroll
        for (int mt = 0; mt < 4; mt++) {
            int r0 = bm + warp_m * 64 + mt * 16 + (lane >> 2);
            #pragma unroll
            for (int nt = 0; nt < 4; nt++) {
                int col = bn + warp_n * 32 + nt * 8 + (lane & 3) * 2;
                *(float2*)(C + (size_t)r0 * Ncols + col)       = make_float2(acc[mt][nt][0], acc[mt][nt][1]);
                *(float2*)(C + (size_t)(r0 + 8) * Ncols + col) = make_float2(acc[mt][nt][2], acc[mt][nt][3]);
            }
        }
    } else if (mode == 1) {
        #pragma unroll
        for (int mt = 0; mt < 4; mt++) {
            int r0 = bm + warp_m * 64 + mt * 16 + (lane >> 2);
            float gsA = g_gp[r0] + g_gp[Tn + r0];
            float gsB = g_gp[r0 + 8] + g_gp[Tn + r0 + 8];
            #pragma unroll
            for (int nt = 0; nt < 4; nt++) {
                int col = bn + warp_n * 32 + nt * 8 + (lane & 3) * 2;
                float2 zA = *(const float2*)(aux1 + (size_t)r0 * HXs + col);
                float2 zB = *(const float2*)(aux1 + (size_t)(r0 + 8) * HXs + col);
                float h0 = fmaxf(zA.x, 0.f) + gsA * zA.x + acc[mt][nt][0];
                float h1 = fmaxf(zA.y, 0.f) + gsA * zA.y + acc[mt][nt][1];
                float h2 = fmaxf(zB.x, 0.f) + gsB * zB.x + acc[mt][nt][2];
                float h3 = fmaxf(zB.y, 0.f) + gsB * zB.y + acc[mt][nt][3];
                __nv_bfloat162 loA, loB;
                __nv_bfloat162 hiA = split_hi2(h0, h1, loA);
                __nv_bfloat162 hiB = split_hi2(h2, h3, loB);
                *(__nv_bfloat162*)(a2o + (size_t)r0 * 2 * Ff + col)            = hiA;
                *(__nv_bfloat162*)(a2o + (size_t)r0 * 2 * Ff + Ff + col)       = loA;
                *(__nv_bfloat162*)(a2o + (size_t)(r0 + 8) * 2 * Ff + col)      = hiB;
                *(__nv_bfloat162*)(a2o + (size_t)(r0 + 8) * 2 * Ff + Ff + col) = loB;
            }
        }
    } else {
        #pragma unroll
        for (int mt = 0; mt < 4; mt++) {
            int r0 = bm + warp_m * 64 + mt * 16 + (lane >> 2);
            float gsA = 1.f + g_gp[r0] + g_gp[Tn + r0];
            float gsB = 1.f + g_gp[r0 + 8] + g_gp[Tn + r0 + 8];
            #pragma unroll
            for (int nt = 0; nt < 4; nt++) {
                int col = bn + warp_n * 32 + nt * 8 + (lane & 3) * 2;
                float2 wA = *(const float2*)(aux2 + (size_t)r0 * WXs + col);
                float2 wB = *(const float2*)(aux2 + (size_t)(r0 + 8) * WXs + col);
                float2 xA = *(const float2*)(aux1 + (size_t)r0 * Dd + col);
                float2 xB = *(const float2*)(aux1 + (size_t)(r0 + 8) * Dd + col);
                *(float2*)(C + (size_t)r0 * Dd + col) = make_float2(
                    xA.x + gsA * wA.x + acc[mt][nt][0], xA.y + gsA * wA.y + acc[mt][nt][1]);
                *(float2*)(C + (size_t)(r0 + 8) * Dd + col) = make_float2(
                    xB.x + gsB * wB.x + acc[mt][nt][2], xB.y + gsB * wB.y + acc[mt][nt][3]);
            }
        }
    }
}

// ---------------- RMS norm (+ split-bf16 A1 build + accumulator init fold) ------------
__global__ __launch_bounds__(256) void k_rms(const float* __restrict__ x,
                                             const float* __restrict__ lnw) {
    if (blockIdx.x == 0) {
        if (threadIdx.x < Bbat * Ee) g_dp[threadIdx.x] = 0.f;
        if (threadIdx.x == 0) g_zl = 0.f;
    }
    int t = blockIdx.x;
    const float* xr = x + (size_t)t * Dd;
    float s = 0.f;
    for (int d = threadIdx.x; d < Dd; d += 256) { float v = xr[d]; s += v * v; }
    __shared__ float red[256];
    red[threadIdx.x] = s; __syncthreads();
    for (int o = 128; o > 0; o >>= 1) {
        if (threadIdx.x < o) red[threadIdx.x] += red[threadIdx.x + o];
        __syncthreads();
    }
    float inv = rsqrtf(red[0] / (float)Dd + 1e-6f);
    __nv_bfloat16* a1 = g_A1 + (size_t)t * 2 * Dd;
    for (int d = threadIdx.x; d < Dd; d += 256) {
        float v = xr[d] * inv * lnw[d];
        g_wi[(size_t)t * Dd + d] = v;
        __nv_bfloat16 hi = __float2bfloat16(v);
        __nv_bfloat16 lo = __float2bfloat16(v - __bfloat162float(hi));
        a1[d] = hi; a1[Dd + d] = lo;
    }
}

// ---------------- B1x build: rows 0..3071 = Wi, rows 3072.. = Ai cols ----------------
__global__ __launch_bounds__(256) void k_splitB1x(const float* __restrict__ Wi,
                                                  const float* __restrict__ Ai) {
    int n = blockIdx.x;
    __nv_bfloat16* b = g_B1x + (size_t)n * 2 * Dd;
    if (n < Ff) {
        const float* wr = Wi + (size_t)n * Dd;
        for (int d = threadIdx.x; d < Dd; d += 256) {
            float v = wr[d];
            __nv_bfloat16 hi = __float2bfloat16(v);
            b[d] = hi; b[Dd + d] = __float2bfloat16(v - __bfloat162float(hi));
        }
    } else {
        int c = n - Ff, e = c >> 4, r = c & 15;
        const float* Ae = Ai + (size_t)e * Dd * 16 + r;
        for (int d = threadIdx.x; d < Dd; d += 256) {
            float v = Ae[d * 16];
            __nv_bfloat16 hi = __float2bfloat16(v);
            b[d] = hi; b[Dd + d] = __float2bfloat16(v - __bfloat162float(hi));
        }
    }
}

// ---------------- B2x build: rows 0..767 = Wo, rows 768.. = Ao cols ----------------
__global__ __launch_bounds__(256) void k_splitB2x(const float* __restrict__ Wo,
                                                  const float* __restrict__ Ao) {
    int n = blockIdx.x;
    __nv_bfloat16* b = g_B2x + (size_t)n * 2 * Ff;
    if (n < Dd) {
        const float* wr = Wo + (size_t)n * Ff;
        for (int f = threadIdx.x; f < Ff; f += 256) {
            float v = wr[f];
            __nv_bfloat16 hi = __float2bfloat16(v);
            b[f] = hi; b[Ff + f] = __float2bfloat16(v - __bfloat162float(hi));
        }
    } else {
        int c = n - Dd, e = c >> 4, r = c & 15;
        const float* Ae = Ao + (size_t)e * Ff * 16 + r;
        for (int f = threadIdx.x; f < Ff; f += 256) {
            float v = Ae[f * 16];
            __nv_bfloat16 hi = __float2bfloat16(v);
            b[f] = hi; b[Ff + f] = __float2bfloat16(v - __bfloat162float(hi));
        }
    }
}

// ---------------- Bd1 build: row f, col c=(e*16+r) -> Bi[e,r,f] ----------------
__global__ __launch_bounds__(256) void k_splitBd1(const float* __restrict__ Bi) {
    int f = blockIdx.x;
    __nv_bfloat16* b = g_Bd1 + (size_t)f * 512;
    for (int c = threadIdx.x; c < 256; c += 256) {
        int e = c >> 4, r = c & 15;
        float v = Bi[(size_t)e * 16 * Ff + (size_t)r * Ff + f];
        __nv_bfloat16 hi = __float2bfloat16(v);
        b[c] = hi; b[256 + c] = __float2bfloat16(v - __bfloat162float(hi));
    }
}
// ---------------- Bd2 build: row d, col c=(e*16+r) -> Bo[e,r,d] ----------------
__global__ __launch_bounds__(256) void k_splitBd2(const float* __restrict__ Bo) {
    int d = blockIdx.x;
    __nv_bfloat16* b = g_Bd2 + (size_t)d * 512;
    for (int c = threadIdx.x; c < 256; c += 256) {
        int e = c >> 4, r = c & 15;
        float v = Bo[(size_t)e * 16 * Dd + (size_t)r * Dd + d];
        __nv_bfloat16 hi = __float2bfloat16(v);
        b[c] = hi; b[256 + c] = __float2bfloat16(v - __bfloat162float(hi));
    }
}

// ---------------- logits = wi_in @ Wg^T (float4 smem) ----------------
__global__ __launch_bounds__(256) void k_logits(const float* __restrict__ Wg,
                                                float* __restrict__ out) {
    __shared__ float4 sWg[(Dd / 4) * 16];
    for (int i = threadIdx.x; i < Dd * 16 / 4; i += 256) {
        int d4 = i / 16, e = i % 16;
        const float* w = Wg + (size_t)e * Dd + d4 * 4;
        sWg[d4 * 16 + e] = make_float4(w[0], w[1], w[2], w[3]);
    }
    __syncthreads();
    int tok = blockIdx.x * 16 + (threadIdx.x >> 4);
    int e = threadIdx.x & 15;
    const float4* wr = (const float4*)(g_wi + (size_t)tok * Dd);
    float s = 0.f;
    #pragma unroll 4
    for (int d4 = 0; d4 < Dd / 4; d4++) {
        float4 xv = wr[d4];
        float4 wv = sWg[d4 * 16 + e];
        s += xv.x * wv.x + xv.y * wv.y + xv.z * wv.z + xv.w * wv.w;
    }
    out[OFF_LOGITS + (size_t)tok * 16 + e] = s;
}

// ---------------- softmax / top2 / gates / aux partials ----------------
__global__ __launch_bounds__(256) void k_gate(const float* __restrict__ rp,
                                              float* __restrict__ out) {
    int t = blockIdx.x * 256 + threadIdx.x;
    int lane = threadIdx.x & 31;
    const float* lg = out + OFF_LOGITS + (size_t)t * 16;
    float l[16];
    float mx = -1e30f;
    #pragma unroll
    for (int e = 0; e < 16; e++) { l[e] = lg[e]; mx = fmaxf(mx, l[e]); }
    float se = 0.f;
    #pragma unroll
    for (int e = 0; e < 16; e++) se += __expf(l[e] - mx);
    float lse = mx + __logf(se);
    out[OFF_ENERGY + t] = -lse;

    int e0 = 0; float b0 = l[0];
    #pragma unroll
    for (int e = 1; e < 16; e++) if (l[e] > b0) { b0 = l[e]; e0 = e; }
    int e1 = -1; float b1 = -1e30f;
    #pragma unroll
    for (int e = 0; e < 16; e++) if (e != e0 && l[e] > b1) { b1 = l[e]; e1 = e; }
    float v0 = __expf(b0 - lse), v1 = __expf(b1 - lse);
    float den = v0 + v1; if (den < 1e-9f) den = 1e-9f;
    float G0 = v0 / den, G1 = v1 / den;
    g_e[t] = e0; g_e[Tn + t] = e1;
    g_gate[t] = G0; g_gate[Tn + t] = G1;
    g_sh1[t] = (rp[Tn + t] < G1 * 5.0f) ? 1 : 0;

    int b = t >> 11;
    float zv = lse * lse;
    #pragma unroll
    for (int o = 16; o > 0; o >>= 1) zv += __shfl_xor_sync(0xffffffffu, zv, o);
    if (lane == 0) atomicAdd(&g_zl, zv);
    #pragma unroll
    for (int e = 0; e < 16; e++) {
        float pv = __expf(l[e] - lse);
        #pragma unroll
        for (int o = 16; o > 0; o >>= 1) pv += __shfl_xor_sync(0xffffffffu, pv, o);
        if (lane == 0) atomicAdd(&g_dp[b * 16 + e], pv);
    }
}

// ---------------- capacity scan ----------------
__global__ void k_scan(float* __restrict__ out) {
    if (threadIdx.x != 0) return;
    int b = blockIdx.x;
    int base = b * Nseq;
    int c0[16];
    #pragma unroll
    for (int e = 0; e < 16; e++) c0[e] = 0;
    for (int n = 0; n < Nseq; n++) {
        int t = base + n;
        int e = g_e[t];
        int pos = c0[e]++;
        bool s = pos < CAPc;
        g_gp[t] = s ? g_gate[t] : 0.f;
        out[OFF_GIDX + t] = s ? (float)e : 0.f;
    }
    int c1[16];
    #pragma unroll
    for (int e = 0; e < 16; e++) {
        int sv = c0[e] < CAPc ? c0[e] : CAPc;
        g_d1[b * 16 + e] = (float)sv / (float)Nseq;
        c1[e] = sv;
    }
    for (int n = 0; n < Nseq; n++) {
        int t = base + n;
        if (g_sh1[t]) {
            int e = g_e[Tn + t];
            int pos = c1[e]++;
            bool s = pos < CAPc;
            g_gp[Tn + t] = s ? g_gate[Tn + t] : 0.f;
            out[OFF_GIDX + Tn + t] = s ? (float)e : 0.f;
        } else {
            g_gp[Tn + t] = 0.f;
            out[OFF_GIDX + Tn + t] = 0.f;
        }
    }
}

// ---------------- aux scalars ----------------
__global__ void k_aux(float* __restrict__ out) {
    __shared__ float red[128];
    int i = threadIdx.x;
    red[i] = (g_dp[i] / (float)Nseq) * g_d1[i];
    __syncthreads();
    for (int o = 64; o > 0; o >>= 1) {
        if (i < o) red[i] += red[i + o];
        __syncthreads();
    }
    if (i == 0) {
        float bal = red[0] * 2.0f;
        float zl = g_zl / (float)Tn;
        out[OFF_BAL] = bal;
        out[OFF_ZL] = zl;
        out[OFF_AUX] = 0.01f * bal + 0.01f * zl;
    }
}

// ---------------- v1: gated u1 -> split bf16 [Tn x 256] ----------------
__global__ __launch_bounds__(256) void k_v1() {
    int t = blockIdx.x * 16 + (threadIdx.x >> 4) + ((threadIdx.x & 15) * 0);
    // simpler: 16 tokens per block, 16 cols per thread pass
    int base = blockIdx.x * 16;
    for (int i = threadIdx.x; i < 16 * 256; i += 256) {
        int tl = base + (i >> 8);
        int c = i & 255;
        int e = c >> 4;
        float g = (e == g_e[tl]) ? g_gp[tl] : (e == g_e[Tn + tl]) ? g_gp[Tn + tl] : 0.f;
        float v = 2.f * g * g_hx[(size_t)tl * HXs + Ff + c];
        __nv_bfloat16 hi = __float2bfloat16(v);
        g_V1[(size_t)tl * 512 + c] = hi;
        g_V1[(size_t)tl * 512 + 256 + c] = __float2bfloat16(v - __bfloat162float(hi));
    }
    (void)t;
}

// ---------------- v2: gated u2 -> split bf16 [Tn x 256] ----------------
__global__ __launch_bounds__(256) void k_v2() {
    int base = blockIdx.x * 16;
    for (int i = threadIdx.x; i < 16 * 256; i += 256) {
        int tl = base + (i >> 8);
        int c = i & 255;
        int e = c >> 4;
        float g = (e == g_e[tl]) ? g_gp[tl] : (e == g_e[Tn + tl]) ? g_gp[Tn + tl] : 0.f;
        float v = 2.f * g * g_wx[(size_t)tl * WXs + Dd + c];
        __nv_bfloat16 hi = __float2bfloat16(v);
        g_V2[(size_t)tl * 512 + c] = hi;
        g_V2[(size_t)tl * 512 + 256 + c] = __float2bfloat16(v - __bfloat162float(hi));
    }
}

// ---------------- launch ----------------
extern "C" void kernel_launch(void* const* d_in, const int* in_sizes, int n_in,
                              void* d_out, int out_size) {
    const float* x   = (const float*)d_in[0];
    const float* rp  = (const float*)d_in[1];
    const float* lnw = (const float*)d_in[2];
    const float* Wg  = (const float*)d_in[3];
    const float* Wi  = (const float*)d_in[4];
    const float* Wo  = (const float*)d_in[5];
    const float* Ai  = (const float*)d_in[6];
    const float* Bi  = (const float*)d_in[7];
    const float* Ao  = (const float*)d_in[8];
    const float* Bo  = (const float*)d_in[9];
    float* out = (float*)d_out;

    cudaFuncSetAttribute(k_tc_gemm, cudaFuncAttributeMaxDynamicSharedMemorySize, SMEM_GEMM);

    __nv_bfloat16 *A1p, *B1xp, *A2p, *B2xp, *V1p, *V2p, *Bd1p, *Bd2p;
    float *hxp, *wxp;
    cudaGetSymbolAddress((void**)&A1p,  g_A1);
    cudaGetSymbolAddress((void**)&B1xp, g_B1x);
    cudaGetSymbolAddress((void**)&A2p,  g_A2);
    cudaGetSymbolAddress((void**)&B2xp, g_B2x);
    cudaGetSymbolAddress((void**)&V1p,  g_V1);
    cudaGetSymbolAddress((void**)&V2p,  g_V2);
    cudaGetSymbolAddress((void**)&Bd1p, g_Bd1);
    cudaGetSymbolAddress((void**)&Bd2p, g_Bd2);
    cudaGetSymbolAddress((void**)&hxp,  g_hx);
    cudaGetSymbolAddress((void**)&wxp,  g_wx);

    // prep
    k_rms<<<Tn, 256>>>(x, lnw);                          // #1
    k_splitB1x<<<N1X, 256>>>(Wi, Ai);                    // #2
    k_splitB2x<<<N2X, 256>>>(Wo, Ao);                    // #3
    // GEMM1: [z | u1all] = A1 @ B1x^T    (ncu slot #4)
    k_tc_gemm<<<dim3(N1X / 128, Tn / 128), 256, SMEM_GEMM>>>(
        A1p, B1xp, hxp, N1X, Dd, Dd / 64, 3 * Dd / 64, 0, nullptr, nullptr, nullptr);
    k_splitBd1<<<Ff, 256>>>(Bi);
    k_splitBd2<<<Dd, 256>>>(Bo);
    // gating chain
    k_logits<<<Tn / 16, 256>>>(Wg, out);
    k_gate<<<Tn / 256, 256>>>(rp, out);
    k_scan<<<Bbat, 32>>>(out);
    k_aux<<<1, 128>>>(out);
    // wi-path delta GEMM with fused h-epilogue -> A2
    k_v1<<<Tn / 16, 256>>>();
    k_tc_gemm<<<dim3(Ff / 128, Tn / 128), 256, SMEM_GEMM>>>(
        V1p, Bd1p, nullptr, Ff, 256, 4, 12, 1, hxp, nullptr, A2p);
    // GEMM2: [w | u2all] = A2 @ B2x^T
    k_tc_gemm<<<dim3(N2X / 128, Tn / 128), 256, SMEM_GEMM>>>(
        A2p, B2xp, wxp, N2X, Ff, Ff / 64, 3 * Ff / 64, 0, nullptr, nullptr, nullptr);
    // wo-path delta GEMM with fused out-epilogue
    k_v2<<<Tn / 16, 256>>>();
    k_tc_gemm<<<dim3(Dd / 128, Tn / 128), 256, SMEM_GEMM>>>(
        V2p, Bd2p, out, Dd, 256, 4, 12, 2, x, wxp, nullptr);
}

// round 13
// speedup vs baseline: 1.6958x; 1.0449x over previous
#include <cuda_runtime.h>
#include <cuda_bf16.h>
#include <math.h>
#include <stdint.h>

// Problem constants
#define Tn 16384            // B*N tokens
#define Dd 768
#define Ff 3072
#define Ee 16
#define CAPc 160
#define Bbat 8
#define Nseq 2048

#define N1X 3328            // GEMM1 N: 3072 z + 256 u1
#define N2X 1024            // GEMM2 N: 768 w + 256 u2
#define HXs 3328            // g_hx row stride
#define WXs 1024            // g_wx row stride

// Output layout (float32, concatenated in reference return order)
#define OFF_AUX    12582912
#define OFF_BAL    12582913
#define OFF_ZL     12582914
#define OFF_LOGITS 12582915ll
#define OFF_ENERGY 12845059ll
#define OFF_GIDX   12861443ll

// ---------------- scratch (device globals; no runtime allocation) ----------------
__device__ float g_wi[(size_t)Tn * Dd];                 // RMS-normed input (fp32)
__device__ float g_hx[(size_t)Tn * HXs];                // [z | u1_all] raw
__device__ float g_wx[(size_t)Tn * WXs];                // [w | u2_all] raw
__device__ __nv_bfloat16 g_A1 [(size_t)Tn * 2 * Dd];    // [wi_hi | wi_lo]
__device__ __nv_bfloat16 g_B1x[(size_t)N1X * 2 * Dd];   // [Wi|Ai rows, hi|lo]
__device__ __nv_bfloat16 g_A2 [(size_t)Tn * 2 * Ff];    // [h_hi | h_lo]
__device__ __nv_bfloat16 g_B2x[(size_t)N2X * 2 * Ff];   // [Wo|Ao rows, hi|lo]
__device__ __nv_bfloat16 g_V1 [(size_t)Tn * 512];       // gated u1 [hi|lo], K=256
__device__ __nv_bfloat16 g_V2 [(size_t)Tn * 512];       // gated u2 [hi|lo]
__device__ __nv_bfloat16 g_Bd1[(size_t)Ff * 512];       // Bi^T rows [hi|lo]
__device__ __nv_bfloat16 g_Bd2[(size_t)Dd * 512];       // Bo^T rows [hi|lo]
__device__ int   g_e  [2 * Tn];
__device__ float g_gate[2 * Tn];
__device__ float g_gp  [2 * Tn];                        // gate after drop (0 if dropped)
__device__ int   g_sh1 [Tn];
__device__ float g_dp[Bbat * Ee];
__device__ float g_d1[Bbat * Ee];
__device__ float g_zl;

// ---------------- PTX helpers (sm_100-safe) ----------------
__device__ __forceinline__ uint32_t s2u(const void* p) {
    uint32_t a;
    asm("{ .reg .u64 t; cvta.to.shared.u64 t, %1; cvt.u32.u64 %0, t; }" : "=r"(a) : "l"(p));
    return a;
}
__device__ __forceinline__ void cpa16(uint32_t s, const void* g) {
    asm volatile("cp.async.cg.shared.global [%0], [%1], 16;\n" :: "r"(s), "l"(g));
}
#define CPA_COMMIT() asm volatile("cp.async.commit_group;\n" ::: "memory")
#define CPA_WAIT1()  asm volatile("cp.async.wait_group 1;\n" ::: "memory")

__device__ __forceinline__ void ldsm4(uint32_t* r, uint32_t a) {
    asm volatile("ldmatrix.sync.aligned.m8n8.x4.shared.b16 {%0,%1,%2,%3}, [%4];"
                 : "=r"(r[0]), "=r"(r[1]), "=r"(r[2]), "=r"(r[3]) : "r"(a));
}
__device__ __forceinline__ void mma16816(float* c, const uint32_t* a, uint32_t b0, uint32_t b1) {
    asm volatile("mma.sync.aligned.m16n8k16.row.col.f32.bf16.bf16.f32 "
                 "{%0,%1,%2,%3}, {%4,%5,%6,%7}, {%8,%9}, {%0,%1,%2,%3};"
                 : "+f"(c[0]), "+f"(c[1]), "+f"(c[2]), "+f"(c[3])
                 : "r"(a[0]), "r"(a[1]), "r"(a[2]), "r"(a[3]), "r"(b0), "r"(b1));
}

#define SWZ(o) ((o) ^ (((o) >> 3) & 0x70))

// GEMM smem: A stages [128][64]bf16 = 16KB (x3), B stages [128][64]bf16 = 16KB (x3)
#define SM_A(s) ((s) * 16384)
#define SM_B(s) (49152 + (s) * 16384)
#define SMEM_GEMM 98304

__device__ __forceinline__ __nv_bfloat162 split_hi2(float a, float b,
                                                    __nv_bfloat162& lo) {
    __nv_bfloat162 hi;
    hi.x = __float2bfloat16(a); hi.y = __float2bfloat16(b);
    lo.x = __float2bfloat16(a - __bfloat162float(hi.x));
    lo.y = __float2bfloat16(b - __bfloat162float(hi.y));
    return hi;
}

// ---------------- mma.sync split-bf16 GEMM: C[m,n] = sum_k A[m,k]*B[n,k] ----------------
// Tile 128x128, K-chunk 64, 3-stage cp.async, 256 threads, 2 CTAs/SM.
// A terms: hi, lo, hi ; B terms: hi, hi, lo (3-term schedule over 2-term storage)
// mode 0: raw store to C (stride Ncols)
// mode 1: h-epilogue: z=aux1 (stride HXs); h=relu(z)+gs*z+acc; write A2 [hi|lo] (a2o)
// mode 2: out-epilogue: out = aux1(x,768) + (1+gs)*aux2(w,WXs) + acc; store C (768)
__global__ __launch_bounds__(256, 2)
void k_tc_gemm(const __nv_bfloat16* __restrict__ A, const __nv_bfloat16* __restrict__ B,
               float* __restrict__ C, int Ncols, int K, int cpt, int KI, int mode,
               const float* __restrict__ aux1, const float* __restrict__ aux2,
               __nv_bfloat16* __restrict__ a2o) {
    extern __shared__ char smem[];
    const uint32_t sb = s2u(smem);
    const int tid = threadIdx.x;
    const int wid = tid >> 5;
    const int lane = tid & 31;
    const int warp_m = wid & 1;          // 2 groups of M=64
    const int warp_n = wid >> 1;         // 4 groups of N=32
    const int bm = blockIdx.y * 128;
    const int bn = blockIdx.x * 128;
    const int K2 = 2 * K;

    // ---- loader precompute: per-thread global pointers + swizzled smem offsets ----
    const __nv_bfloat16* agp[4];
    const __nv_bfloat16* bgp[4];
    uint32_t asm_[4], bsm_[4];
    #pragma unroll
    for (int j = 0; j < 4; j++) {
        int idx = tid + 256 * j, row = idx >> 3, seg = idx & 7;
        agp[j] = A + (size_t)(bm + row) * K2 + seg * 8;
        bgp[j] = B + (size_t)(bn + row) * K2 + seg * 8;
        uint32_t so = SWZ(row * 128 + seg * 16);
        asm_[j] = sb + so;
        bsm_[j] = sb + 49152 + so;
    }

    // ---- compute precompute: row offsets + swizzle XOR masks (row-only dependent) ----
    const uint32_t hiA = (lane >> 4) << 4;
    const uint32_t hiB = ((lane >> 3) & 1) << 4;
    uint32_t aro[4], axm[4];
    #pragma unroll
    for (int mt = 0; mt < 4; mt++) {
        int row = warp_m * 64 + mt * 16 + (lane & 15);
        aro[mt] = row * 128;
        axm[mt] = (row & 7) << 4;
    }
    uint32_t bro[2], bxm[2];
    #pragma unroll
    for (int g = 0; g < 2; g++) {
        int nr = warp_n * 32 + g * 16 + ((lane >> 4) << 3) + (lane & 7);
        bro[g] = nr * 128;
        bxm[g] = (nr & 7) << 4;
    }

    float acc[4][4][4];
    #pragma unroll
    for (int i = 0; i < 4; i++)
        #pragma unroll
        for (int j = 0; j < 4; j++)
            #pragma unroll
            for (int q = 0; q < 4; q++) acc[i][j][q] = 0.f;

    // prologue: stages 0,1
    #pragma unroll
    for (int c = 0; c < 2; c++) {
        int t = c / cpt;
        int goA = (t == 1 ? K : 0) + (c - t * cpt) * 64;
        int goB = (t == 2 ? K : 0) + (c - t * cpt) * 64;
        #pragma unroll
        for (int j = 0; j < 4; j++) cpa16(asm_[j] + c * 16384, agp[j] + goA);
        #pragma unroll
        for (int j = 0; j < 4; j++) cpa16(bsm_[j] + c * 16384, bgp[j] + goB);
        CPA_COMMIT();
    }

    for (int i = 0; i < KI; i++) {
        const int si = i % 3;
        CPA_WAIT1();
        __syncthreads();

        const int j = i + 2;
        if (j < KI) {
            const int sj = j % 3;
            int t = j / cpt;
            int goA = (t == 1 ? K : 0) + (j - t * cpt) * 64;
            int goB = (t == 2 ? K : 0) + (j - t * cpt) * 64;
            #pragma unroll
            for (int jj = 0; jj < 4; jj++) cpa16(asm_[jj] + sj * 16384, agp[jj] + goA);
            #pragma unroll
            for (int jj = 0; jj < 4; jj++) cpa16(bsm_[jj] + sj * 16384, bgp[jj] + goB);
        }
        CPA_COMMIT();

        // per-chunk stage bases
        uint32_t saA[4], sBb[2];
        #pragma unroll
        for (int mt = 0; mt < 4; mt++) saA[mt] = sb + si * 16384 + aro[mt];
        #pragma unroll
        for (int g = 0; g < 2; g++) sBb[g] = sb + 49152 + si * 16384 + bro[g];

        #pragma unroll
        for (int ks = 0; ks < 4; ks++) {
            uint32_t a[4][4];
            #pragma unroll
            for (int mt = 0; mt < 4; mt++)
                ldsm4(a[mt], saA[mt] + ((ks * 32 + hiA) ^ axm[mt]));
            uint32_t b[2][4];
            #pragma unroll
            for (int g = 0; g < 2; g++)
                ldsm4(b[g], sBb[g] + ((ks * 32 + hiB) ^ bxm[g]));
            #pragma unroll
            for (int mt = 0; mt < 4; mt++)
                #pragma unroll
                for (int nt = 0; nt < 4; nt++) {
                    int g = nt >> 1, hf = (nt & 1) << 1;
                    mma16816(acc[mt][nt], a[mt], b[g][hf], b[g][hf + 1]);
                }
        }
        __syncthreads();
    }

    if (mode == 0) {
        #pragma unroll
        for (int mt = 0; mt < 4; mt++) {
            int r0 = bm + warp_m * 64 + mt * 16 + (lane >> 2);
            #pragma unroll
            for (int nt = 0; nt < 4; nt++) {
                int col = bn + warp_n * 32 + nt * 8 + (lane & 3) * 2;
                *(float2*)(C + (size_t)r0 * Ncols + col)       = make_float2(acc[mt][nt][0], acc[mt][nt][1]);
                *(float2*)(C + (size_t)(r0 + 8) * Ncols + col) = make_float2(acc[mt][nt][2], acc[mt][nt][3]);
            }
        }
    } else if (mode == 1) {
        #pragma unroll
        for (int mt = 0; mt < 4; mt++) {
            int r0 = bm + warp_m * 64 + mt * 16 + (lane >> 2);
            float gsA = g_gp[r0] + g_gp[Tn + r0];
            float gsB = g_gp[r0 + 8] + g_gp[Tn + r0 + 8];
            #pragma unroll
            for (int nt = 0; nt < 4; nt++) {
                int col = bn + warp_n * 32 + nt * 8 + (lane & 3) * 2;
                float2 zA = *(const float2*)(aux1 + (size_t)r0 * HXs + col);
                float2 zB = *(const float2*)(aux1 + (size_t)(r0 + 8) * HXs + col);
                float h0 = fmaxf(zA.x, 0.f) + gsA * zA.x + acc[mt][nt][0];
                float h1 = fmaxf(zA.y, 0.f) + gsA * zA.y + acc[mt][nt][1];
                float h2 = fmaxf(zB.x, 0.f) + gsB * zB.x + acc[mt][nt][2];
                float h3 = fmaxf(zB.y, 0.f) + gsB * zB.y + acc[mt][nt][3];
                __nv_bfloat162 loA, loB;
                __nv_bfloat162 hiA2 = split_hi2(h0, h1, loA);
                __nv_bfloat162 hiB2 = split_hi2(h2, h3, loB);
                *(__nv_bfloat162*)(a2o + (size_t)r0 * 2 * Ff + col)            = hiA2;
                *(__nv_bfloat162*)(a2o + (size_t)r0 * 2 * Ff + Ff + col)       = loA;
                *(__nv_bfloat162*)(a2o + (size_t)(r0 + 8) * 2 * Ff + col)      = hiB2;
                *(__nv_bfloat162*)(a2o + (size_t)(r0 + 8) * 2 * Ff + Ff + col) = loB;
            }
        }
    } else {
        #pragma unroll
        for (int mt = 0; mt < 4; mt++) {
            int r0 = bm + warp_m * 64 + mt * 16 + (lane >> 2);
            float gsA = 1.f + g_gp[r0] + g_gp[Tn + r0];
            float gsB = 1.f + g_gp[r0 + 8] + g_gp[Tn + r0 + 8];
            #pragma unroll
            for (int nt = 0; nt < 4; nt++) {
                int col = bn + warp_n * 32 + nt * 8 + (lane & 3) * 2;
                float2 wA = *(const float2*)(aux2 + (size_t)r0 * WXs + col);
                float2 wB = *(const float2*)(aux2 + (size_t)(r0 + 8) * WXs + col);
                float2 xA = *(const float2*)(aux1 + (size_t)r0 * Dd + col);
                float2 xB = *(const float2*)(aux1 + (size_t)(r0 + 8) * Dd + col);
                *(float2*)(C + (size_t)r0 * Dd + col) = make_float2(
                    xA.x + gsA * wA.x + acc[mt][nt][0], xA.y + gsA * wA.y + acc[mt][nt][1]);
                *(float2*)(C + (size_t)(r0 + 8) * Dd + col) = make_float2(
                    xB.x + gsB * wB.x + acc[mt][nt][2], xB.y + gsB * wB.y + acc[mt][nt][3]);
            }
        }
    }
}

// ---------------- RMS norm (+ split-bf16 A1 build + accumulator init fold) ------------
__global__ __launch_bounds__(256) void k_rms(const float* __restrict__ x,
                                             const float* __restrict__ lnw) {
    if (blockIdx.x == 0) {
        if (threadIdx.x < Bbat * Ee) g_dp[threadIdx.x] = 0.f;
        if (threadIdx.x == 0) g_zl = 0.f;
    }
    int t = blockIdx.x;
    const float* xr = x + (size_t)t * Dd;
    float s = 0.f;
    for (int d = threadIdx.x; d < Dd; d += 256) { float v = xr[d]; s += v * v; }
    __shared__ float red[256];
    red[threadIdx.x] = s; __syncthreads();
    for (int o = 128; o > 0; o >>= 1) {
        if (threadIdx.x < o) red[threadIdx.x] += red[threadIdx.x + o];
        __syncthreads();
    }
    float inv = rsqrtf(red[0] / (float)Dd + 1e-6f);
    __nv_bfloat16* a1 = g_A1 + (size_t)t * 2 * Dd;
    for (int d = threadIdx.x; d < Dd; d += 256) {
        float v = xr[d] * inv * lnw[d];
        g_wi[(size_t)t * Dd + d] = v;
        __nv_bfloat16 hi = __float2bfloat16(v);
        __nv_bfloat16 lo = __float2bfloat16(v - __bfloat162float(hi));
        a1[d] = hi; a1[Dd + d] = lo;
    }
}

// ---------------- B1x build: rows 0..3071 = Wi, rows 3072.. = Ai cols ----------------
__global__ __launch_bounds__(256) void k_splitB1x(const float* __restrict__ Wi,
                                                  const float* __restrict__ Ai) {
    int n = blockIdx.x;
    __nv_bfloat16* b = g_B1x + (size_t)n * 2 * Dd;
    if (n < Ff) {
        const float* wr = Wi + (size_t)n * Dd;
        for (int d = threadIdx.x; d < Dd; d += 256) {
            float v = wr[d];
            __nv_bfloat16 hi = __float2bfloat16(v);
            b[d] = hi; b[Dd + d] = __float2bfloat16(v - __bfloat162float(hi));
        }
    } else {
        int c = n - Ff, e = c >> 4, r = c & 15;
        const float* Ae = Ai + (size_t)e * Dd * 16 + r;
        for (int d = threadIdx.x; d < Dd; d += 256) {
            float v = Ae[d * 16];
            __nv_bfloat16 hi = __float2bfloat16(v);
            b[d] = hi; b[Dd + d] = __float2bfloat16(v - __bfloat162float(hi));
        }
    }
}

// ---------------- B2x build: rows 0..767 = Wo, rows 768.. = Ao cols ----------------
__global__ __launch_bounds__(256) void k_splitB2x(const float* __restrict__ Wo,
                                                  const float* __restrict__ Ao) {
    int n = blockIdx.x;
    __nv_bfloat16* b = g_B2x + (size_t)n * 2 * Ff;
    if (n < Dd) {
        const float* wr = Wo + (size_t)n * Ff;
        for (int f = threadIdx.x; f < Ff; f += 256) {
            float v = wr[f];
            __nv_bfloat16 hi = __float2bfloat16(v);
            b[f] = hi; b[Ff + f] = __float2bfloat16(v - __bfloat162float(hi));
        }
    } else {
        int c = n - Dd, e = c >> 4, r = c & 15;
        const float* Ae = Ao + (size_t)e * Ff * 16 + r;
        for (int f = threadIdx.x; f < Ff; f += 256) {
            float v = Ae[f * 16];
            __nv_bfloat16 hi = __float2bfloat16(v);
            b[f] = hi; b[Ff + f] = __float2bfloat16(v - __bfloat162float(hi));
        }
    }
}

// ---------------- Bd1 build: row f, col c=(e*16+r) -> Bi[e,r,f] ----------------
__global__ __launch_bounds__(256) void k_splitBd1(const float* __restrict__ Bi) {
    int f = blockIdx.x;
    __nv_bfloat16* b = g_Bd1 + (size_t)f * 512;
    for (int c = threadIdx.x; c < 256; c += 256) {
        int e = c >> 4, r = c & 15;
        float v = Bi[(size_t)e * 16 * Ff + (size_t)r * Ff + f];
        __nv_bfloat16 hi = __float2bfloat16(v);
        b[c] = hi; b[256 + c] = __float2bfloat16(v - __bfloat162float(hi));
    }
}
// ---------------- Bd2 build: row d, col c=(e*16+r) -> Bo[e,r,d] ----------------
__global__ __launch_bounds__(256) void k_splitBd2(const float* __restrict__ Bo) {
    int d = blockIdx.x;
    __nv_bfloat16* b = g_Bd2 + (size_t)d * 512;
    for (int c = threadIdx.x; c < 256; c += 256) {
        int e = c >> 4, r = c & 15;
        float v = Bo[(size_t)e * 16 * Dd + (size_t)r * Dd + d];
        __nv_bfloat16 hi = __float2bfloat16(v);
        b[c] = hi; b[256 + c] = __float2bfloat16(v - __bfloat162float(hi));
    }
}

// ---------------- logits = wi_in @ Wg^T (float4 smem) ----------------
__global__ __launch_bounds__(256) void k_logits(const float* __restrict__ Wg,
                                                float* __restrict__ out) {
    __shared__ float4 sWg[(Dd / 4) * 16];
    for (int i = threadIdx.x; i < Dd * 16 / 4; i += 256) {
        int d4 = i / 16, e = i % 16;
        const float* w = Wg + (size_t)e * Dd + d4 * 4;
        sWg[d4 * 16 + e] = make_float4(w[0], w[1], w[2], w[3]);
    }
    __syncthreads();
    int tok = blockIdx.x * 16 + (threadIdx.x >> 4);
    int e = threadIdx.x & 15;
    const float4* wr = (const float4*)(g_wi + (size_t)tok * Dd);
    float s = 0.f;
    #pragma unroll 4
    for (int d4 = 0; d4 < Dd / 4; d4++) {
        float4 xv = wr[d4];
        float4 wv = sWg[d4 * 16 + e];
        s += xv.x * wv.x + xv.y * wv.y + xv.z * wv.z + xv.w * wv.w;
    }
    out[OFF_LOGITS + (size_t)tok * 16 + e] = s;
}

// ---------------- softmax / top2 / gates / aux partials ----------------
__global__ __launch_bounds__(256) void k_gate(const float* __restrict__ rp,
                                              float* __restrict__ out) {
    int t = blockIdx.x * 256 + threadIdx.x;
    int lane = threadIdx.x & 31;
    const float* lg = out + OFF_LOGITS + (size_t)t * 16;
    float l[16];
    float mx = -1e30f;
    #pragma unroll
    for (int e = 0; e < 16; e++) { l[e] = lg[e]; mx = fmaxf(mx, l[e]); }
    float se = 0.f;
    #pragma unroll
    for (int e = 0; e < 16; e++) se += __expf(l[e] - mx);
    float lse = mx + __logf(se);
    out[OFF_ENERGY + t] = -lse;

    int e0 = 0; float b0 = l[0];
    #pragma unroll
    for (int e = 1; e < 16; e++) if (l[e] > b0) { b0 = l[e]; e0 = e; }
    int e1 = -1; float b1 = -1e30f;
    #pragma unroll
    for (int e = 0; e < 16; e++) if (e != e0 && l[e] > b1) { b1 = l[e]; e1 = e; }
    float v0 = __expf(b0 - lse), v1 = __expf(b1 - lse);
    float den = v0 + v1; if (den < 1e-9f) den = 1e-9f;
    float G0 = v0 / den, G1 = v1 / den;
    g_e[t] = e0; g_e[Tn + t] = e1;
    g_gate[t] = G0; g_gate[Tn + t] = G1;
    g_sh1[t] = (rp[Tn + t] < G1 * 5.0f) ? 1 : 0;

    int b = t >> 11;
    float zv = lse * lse;
    #pragma unroll
    for (int o = 16; o > 0; o >>= 1) zv += __shfl_xor_sync(0xffffffffu, zv, o);
    if (lane == 0) atomicAdd(&g_zl, zv);
    #pragma unroll
    for (int e = 0; e < 16; e++) {
        float pv = __expf(l[e] - lse);
        #pragma unroll
        for (int o = 16; o > 0; o >>= 1) pv += __shfl_xor_sync(0xffffffffu, pv, o);
        if (lane == 0) atomicAdd(&g_dp[b * 16 + e], pv);
    }
}

// ---------------- capacity scan ----------------
__global__ void k_scan(float* __restrict__ out) {
    if (threadIdx.x != 0) return;
    int b = blockIdx.x;
    int base = b * Nseq;
    int c0[16];
    #pragma unroll
    for (int e = 0; e < 16; e++) c0[e] = 0;
    for (int n = 0; n < Nseq; n++) {
        int t = base + n;
        int e = g_e[t];
        int pos = c0[e]++;
        bool s = pos < CAPc;
        g_gp[t] = s ? g_gate[t] : 0.f;
        out[OFF_GIDX + t] = s ? (float)e : 0.f;
    }
    int c1[16];
    #pragma unroll
    for (int e = 0; e < 16; e++) {
        int sv = c0[e] < CAPc ? c0[e] : CAPc;
        g_d1[b * 16 + e] = (float)sv / (float)Nseq;
        c1[e] = sv;
    }
    for (int n = 0; n < Nseq; n++) {
        int t = base + n;
        if (g_sh1[t]) {
            int e = g_e[Tn + t];
            int pos = c1[e]++;
            bool s = pos < CAPc;
            g_gp[Tn + t] = s ? g_gate[Tn + t] : 0.f;
            out[OFF_GIDX + Tn + t] = s ? (float)e : 0.f;
        } else {
            g_gp[Tn + t] = 0.f;
            out[OFF_GIDX + Tn + t] = 0.f;
        }
    }
}

// ---------------- aux scalars ----------------
__global__ void k_aux(float* __restrict__ out) {
    __shared__ float red[128];
    int i = threadIdx.x;
    red[i] = (g_dp[i] / (float)Nseq) * g_d1[i];
    __syncthreads();
    for (int o = 64; o > 0; o >>= 1) {
        if (i < o) red[i] += red[i + o];
        __syncthreads();
    }
    if (i == 0) {
        float bal = red[0] * 2.0f;
        float zl = g_zl / (float)Tn;
        out[OFF_BAL] = bal;
        out[OFF_ZL] = zl;
        out[OFF_AUX] = 0.01f * bal + 0.01f * zl;
    }
}

// ---------------- v1: gated u1 -> split bf16 [Tn x 256] ----------------
__global__ __launch_bounds__(256) void k_v1() {
    int base = blockIdx.x * 16;
    for (int i = threadIdx.x; i < 16 * 256; i += 256) {
        int tl = base + (i >> 8);
        int c = i & 255;
        int e = c >> 4;
        float g = (e == g_e[tl]) ? g_gp[tl] : (e == g_e[Tn + tl]) ? g_gp[Tn + tl] : 0.f;
        float v = 2.f * g * g_hx[(size_t)tl * HXs + Ff + c];
        __nv_bfloat16 hi = __float2bfloat16(v);
        g_V1[(size_t)tl * 512 + c] = hi;
        g_V1[(size_t)tl * 512 + 256 + c] = __float2bfloat16(v - __bfloat162float(hi));
    }
}

// ---------------- v2: gated u2 -> split bf16 [Tn x 256] ----------------
__global__ __launch_bounds__(256) void k_v2() {
    int base = blockIdx.x * 16;
    for (int i = threadIdx.x; i < 16 * 256; i += 256) {
        int tl = base + (i >> 8);
        int c = i & 255;
        int e = c >> 4;
        float g = (e == g_e[tl]) ? g_gp[tl] : (e == g_e[Tn + tl]) ? g_gp[Tn + tl] : 0.f;
        float v = 2.f * g * g_wx[(size_t)tl * WXs + Dd + c];
        __nv_bfloat16 hi = __float2bfloat16(v);
        g_V2[(size_t)tl * 512 + c] = hi;
        g_V2[(size_t)tl * 512 + 256 + c] = __float2bfloat16(v - __bfloat162float(hi));
    }
}

// ---------------- launch ----------------
extern "C" void kernel_launch(void* const* d_in, const int* in_sizes, int n_in,
                              void* d_out, int out_size) {
    const float* x   = (const float*)d_in[0];
    const float* rp  = (const float*)d_in[1];
    const float* lnw = (const float*)d_in[2];
    const float* Wg  = (const float*)d_in[3];
    const float* Wi  = (const float*)d_in[4];
    const float* Wo  = (const float*)d_in[5];
    const float* Ai  = (const float*)d_in[6];
    const float* Bi  = (const float*)d_in[7];
    const float* Ao  = (const float*)d_in[8];
    const float* Bo  = (const float*)d_in[9];
    float* out = (float*)d_out;

    cudaFuncSetAttribute(k_tc_gemm, cudaFuncAttributeMaxDynamicSharedMemorySize, SMEM_GEMM);

    __nv_bfloat16 *A1p, *B1xp, *A2p, *B2xp, *V1p, *V2p, *Bd1p, *Bd2p;
    float *hxp, *wxp;
    cudaGetSymbolAddress((void**)&A1p,  g_A1);
    cudaGetSymbolAddress((void**)&B1xp, g_B1x);
    cudaGetSymbolAddress((void**)&A2p,  g_A2);
    cudaGetSymbolAddress((void**)&B2xp, g_B2x);
    cudaGetSymbolAddress((void**)&V1p,  g_V1);
    cudaGetSymbolAddress((void**)&V2p,  g_V2);
    cudaGetSymbolAddress((void**)&Bd1p, g_Bd1);
    cudaGetSymbolAddress((void**)&Bd2p, g_Bd2);
    cudaGetSymbolAddress((void**)&hxp,  g_hx);
    cudaGetSymbolAddress((void**)&wxp,  g_wx);

    // prep
    k_rms<<<Tn, 256>>>(x, lnw);                          // #1
    k_splitB1x<<<N1X, 256>>>(Wi, Ai);                    // #2
    k_splitB2x<<<N2X, 256>>>(Wo, Ao);                    // #3
    // GEMM1: [z | u1all] = A1 @ B1x^T    (ncu slot #4)
    k_tc_gemm<<<dim3(N1X / 128, Tn / 128), 256, SMEM_GEMM>>>(
        A1p, B1xp, hxp, N1X, Dd, Dd / 64, 3 * Dd / 64, 0, nullptr, nullptr, nullptr);
    k_splitBd1<<<Ff, 256>>>(Bi);
    k_splitBd2<<<Dd, 256>>>(Bo);
    // gating chain
    k_logits<<<Tn / 16, 256>>>(Wg, out);
    k_gate<<<Tn / 256, 256>>>(rp, out);
    k_scan<<<Bbat, 32>>>(out);
    k_aux<<<1, 128>>>(out);
    // wi-path delta GEMM with fused h-epilogue -> A2
    k_v1<<<Tn / 16, 256>>>();
    k_tc_gemm<<<dim3(Ff / 128, Tn / 128), 256, SMEM_GEMM>>>(
        V1p, Bd1p, nullptr, Ff, 256, 4, 12, 1, hxp, nullptr, A2p);
    // GEMM2: [w | u2all] = A2 @ B2x^T
    k_tc_gemm<<<dim3(N2X / 128, Tn / 128), 256, SMEM_GEMM>>>(
        A2p, B2xp, wxp, N2X, Ff, Ff / 64, 3 * Ff / 64, 0, nullptr, nullptr, nullptr);
    // wo-path delta GEMM with fused out-epilogue
    k_v2<<<Tn / 16, 256>>>();
    k_tc_gemm<<<dim3(Dd / 128, Tn / 128), 256, SMEM_GEMM>>>(
        V2p, Bd2p, out, Dd, 256, 4, 12, 2, x, wxp, nullptr);
}

// round 14
// speedup vs baseline: 1.6967x; 1.0005x over previous
#include <cuda_runtime.h>
#include <cuda_bf16.h>
#include <math.h>
#include <stdint.h>

// Problem constants
#define Tn 16384            // B*N tokens
#define Dd 768
#define Ff 3072
#define Ee 16
#define CAPc 160
#define Bbat 8
#define Nseq 2048

#define N1X 3328            // GEMM1 N: 3072 z + 256 u1
#define N2X 1024            // GEMM2 N: 768 w + 256 u2
#define HXs 3328            // g_hx row stride
#define WXs 1024            // g_wx row stride

// Output layout (float32, concatenated in reference return order)
#define OFF_AUX    12582912
#define OFF_BAL    12582913
#define OFF_ZL     12582914
#define OFF_LOGITS 12582915ll
#define OFF_ENERGY 12845059ll
#define OFF_GIDX   12861443ll

// ---------------- scratch (device globals; no runtime allocation) ----------------
__device__ float g_wi[(size_t)Tn * Dd];                 // RMS-normed input (fp32)
__device__ float g_hx[(size_t)Tn * HXs];                // [z | u1_all] raw
__device__ float g_wx[(size_t)Tn * WXs];                // [w | u2_all] raw
__device__ __nv_bfloat16 g_A1 [(size_t)Tn * 2 * Dd];    // [wi_hi | wi_lo]
__device__ __nv_bfloat16 g_B1x[(size_t)N1X * 2 * Dd];   // [Wi|Ai rows, hi|lo]
__device__ __nv_bfloat16 g_A2 [(size_t)Tn * 2 * Ff];    // [h_hi | h_lo]
__device__ __nv_bfloat16 g_B2x[(size_t)N2X * 2 * Ff];   // [Wo|Ao rows, hi|lo]
__device__ __nv_bfloat16 g_V1 [(size_t)Tn * 512];       // gated u1 [hi|lo], K=256
__device__ __nv_bfloat16 g_V2 [(size_t)Tn * 512];       // gated u2 [hi|lo]
__device__ __nv_bfloat16 g_Bd1[(size_t)Ff * 512];       // Bi^T rows [hi|lo]
__device__ __nv_bfloat16 g_Bd2[(size_t)Dd * 512];       // Bo^T rows [hi|lo]
__device__ int   g_e  [2 * Tn];
__device__ float g_gate[2 * Tn];
__device__ float g_gp  [2 * Tn];                        // gate after drop (0 if dropped)
__device__ int   g_sh1 [Tn];
__device__ float g_dp[Bbat * Ee];
__device__ float g_d1[Bbat * Ee];
__device__ float g_zl;

// ---------------- PTX helpers (sm_100-safe) ----------------
__device__ __forceinline__ uint32_t s2u(const void* p) {
    uint32_t a;
    asm("{ .reg .u64 t; cvta.to.shared.u64 t, %1; cvt.u32.u64 %0, t; }" : "=r"(a) : "l"(p));
    return a;
}
__device__ __forceinline__ void cpa16(uint32_t s, const void* g) {
    asm volatile("cp.async.cg.shared.global [%0], [%1], 16;\n" :: "r"(s), "l"(g));
}
#define CPA_COMMIT() asm volatile("cp.async.commit_group;\n" ::: "memory")
#define CPA_WAIT1()  asm volatile("cp.async.wait_group 1;\n" ::: "memory")

__device__ __forceinline__ void ldsm4(uint32_t* r, uint32_t a) {
    asm volatile("ldmatrix.sync.aligned.m8n8.x4.shared.b16 {%0,%1,%2,%3}, [%4];"
                 : "=r"(r[0]), "=r"(r[1]), "=r"(r[2]), "=r"(r[3]) : "r"(a));
}
__device__ __forceinline__ void mma16816(float* c, const uint32_t* a, uint32_t b0, uint32_t b1) {
    asm volatile("mma.sync.aligned.m16n8k16.row.col.f32.bf16.bf16.f32 "
                 "{%0,%1,%2,%3}, {%4,%5,%6,%7}, {%8,%9}, {%0,%1,%2,%3};"
                 : "+f"(c[0]), "+f"(c[1]), "+f"(c[2]), "+f"(c[3])
                 : "r"(a[0]), "r"(a[1]), "r"(a[2]), "r"(a[3]), "r"(b0), "r"(b1));
}

#define SWZ(o) ((o) ^ (((o) >> 3) & 0x70))

// GEMM smem: A stages [128][64]bf16 = 16KB (x3), B stages [128][64]bf16 = 16KB (x3)
#define SM_A(s) ((s) * 16384)
#define SM_B(s) (49152 + (s) * 16384)
#define SMEM_GEMM 98304

__device__ __forceinline__ __nv_bfloat162 split_hi2(float a, float b,
                                                    __nv_bfloat162& lo) {
    __nv_bfloat162 hi;
    hi.x = __float2bfloat16(a); hi.y = __float2bfloat16(b);
    lo.x = __float2bfloat16(a - __bfloat162float(hi.x));
    lo.y = __float2bfloat16(b - __bfloat162float(hi.y));
    return hi;
}

// ---------------- mma.sync split-bf16 GEMM: C[m,n] = sum_k A[m,k]*B[n,k] ----------------
// Tile 128x128, K-chunk 64, 3-stage cp.async, 256 threads, 2 CTAs/SM.
// A terms: hi, lo, hi ; B terms: hi, hi, lo (3-term schedule over 2-term storage)
// mode 0: raw store to C (stride Ncols)
// mode 1: h-epilogue: z=aux1 (stride HXs); h=relu(z)+gs*z+acc; write A2 [hi|lo] (a2o)
// mode 2: out-epilogue: out = aux1(x,768) + (1+gs)*aux2(w,WXs) + acc; store C (768)
__global__ __launch_bounds__(256, 2)
void k_tc_gemm(const __nv_bfloat16* __restrict__ A, const __nv_bfloat16* __restrict__ B,
               float* __restrict__ C, int Ncols, int K, int cpt, int KI, int mode,
               const float* __restrict__ aux1, const float* __restrict__ aux2,
               __nv_bfloat16* __restrict__ a2o) {
    extern __shared__ char smem[];
    const uint32_t sb = s2u(smem);
    const int tid = threadIdx.x;
    const int wid = tid >> 5;
    const int lane = tid & 31;
    const int warp_m = wid & 1;          // 2 groups of M=64
    const int warp_n = wid >> 1;         // 4 groups of N=32
    const int bm = blockIdx.y * 128;
    const int bn = blockIdx.x * 128;
    const int K2 = 2 * K;

    // ---- loader precompute: per-thread global pointers + swizzled smem offsets ----
    const __nv_bfloat16* agp[4];
    const __nv_bfloat16* bgp[4];
    uint32_t asm_[4], bsm_[4];
    #pragma unroll
    for (int j = 0; j < 4; j++) {
        int idx = tid + 256 * j, row = idx >> 3, seg = idx & 7;
        agp[j] = A + (size_t)(bm + row) * K2 + seg * 8;
        bgp[j] = B + (size_t)(bn + row) * K2 + seg * 8;
        uint32_t so = SWZ(row * 128 + seg * 16);
        asm_[j] = sb + so;
        bsm_[j] = sb + 49152 + so;
    }

    // ---- compute precompute: row offsets + swizzle XOR masks (row-only dependent) ----
    const uint32_t hiA = (lane >> 4) << 4;
    const uint32_t hiB = ((lane >> 3) & 1) << 4;
    uint32_t aro[4], axm[4];
    #pragma unroll
    for (int mt = 0; mt < 4; mt++) {
        int row = warp_m * 64 + mt * 16 + (lane & 15);
        aro[mt] = row * 128;
        axm[mt] = (row & 7) << 4;
    }
    uint32_t bro[2], bxm[2];
    #pragma unroll
    for (int g = 0; g < 2; g++) {
        int nr = warp_n * 32 + g * 16 + ((lane >> 4) << 3) + (lane & 7);
        bro[g] = nr * 128;
        bxm[g] = (nr & 7) << 4;
    }

    float acc[4][4][4];
    #pragma unroll
    for (int i = 0; i < 4; i++)
        #pragma unroll
        for (int j = 0; j < 4; j++)
            #pragma unroll
            for (int q = 0; q < 4; q++) acc[i][j][q] = 0.f;

    // prologue: stages 0,1
    #pragma unroll
    for (int c = 0; c < 2; c++) {
        int t = c / cpt;
        int goA = (t == 1 ? K : 0) + (c - t * cpt) * 64;
        int goB = (t == 2 ? K : 0) + (c - t * cpt) * 64;
        #pragma unroll
        for (int j = 0; j < 4; j++) cpa16(asm_[j] + c * 16384, agp[j] + goA);
        #pragma unroll
        for (int j = 0; j < 4; j++) cpa16(bsm_[j] + c * 16384, bgp[j] + goB);
        CPA_COMMIT();
    }

    for (int i = 0; i < KI; i++) {
        const int si = i % 3;
        CPA_WAIT1();
        __syncthreads();

        const int j = i + 2;
        if (j < KI) {
            const int sj = j % 3;
            int t = j / cpt;
            int goA = (t == 1 ? K : 0) + (j - t * cpt) * 64;
            int goB = (t == 2 ? K : 0) + (j - t * cpt) * 64;
            #pragma unroll
            for (int jj = 0; jj < 4; jj++) cpa16(asm_[jj] + sj * 16384, agp[jj] + goA);
            #pragma unroll
            for (int jj = 0; jj < 4; jj++) cpa16(bsm_[jj] + sj * 16384, bgp[jj] + goB);
        }
        CPA_COMMIT();

        // per-chunk stage bases
        uint32_t saA[4], sBb[2];
        #pragma unroll
        for (int mt = 0; mt < 4; mt++) saA[mt] = sb + si * 16384 + aro[mt];
        #pragma unroll
        for (int g = 0; g < 2; g++) sBb[g] = sb + 49152 + si * 16384 + bro[g];

        #pragma unroll
        for (int ks = 0; ks < 4; ks++) {
            uint32_t a[4][4];
            #pragma unroll
            for (int mt = 0; mt < 4; mt++)
                ldsm4(a[mt], saA[mt] + ((ks * 32 + hiA) ^ axm[mt]));
            uint32_t b[2][4];
            #pragma unroll
            for (int g = 0; g < 2; g++)
                ldsm4(b[g], sBb[g] + ((ks * 32 + hiB) ^ bxm[g]));
            #pragma unroll
            for (int mt = 0; mt < 4; mt++)
                #pragma unroll
                for (int nt = 0; nt < 4; nt++) {
                    int g = nt >> 1, hf = (nt & 1) << 1;
                    mma16816(acc[mt][nt], a[mt], b[g][hf], b[g][hf + 1]);
                }
        }
        __syncthreads();
    }

    if (mode == 0) {
        #pragma unroll
        for (int mt = 0; mt < 4; mt++) {
            int r0 = bm + warp_m * 64 + mt * 16 + (lane >> 2);
            #pragma unroll
            for (int nt = 0; nt < 4; nt++) {
                int col = bn + warp_n * 32 + nt * 8 + (lane & 3) * 2;
                *(float2*)(C + (size_t)r0 * Ncols + col)       = make_float2(acc[mt][nt][0], acc[mt][nt][1]);
                *(float2*)(C + (size_t)(r0 + 8) * Ncols + col) = make_float2(acc[mt][nt][2], acc[mt][nt][3]);
            }
        }
    } else if (mode == 1) {
        #pragma unroll
        for (int mt = 0; mt < 4; mt++) {
            int r0 = bm + warp_m * 64 + mt * 16 + (lane >> 2);
            float gsA = g_gp[r0] + g_gp[Tn + r0];
            float gsB = g_gp[r0 + 8] + g_gp[Tn + r0 + 8];
            #pragma unroll
            for (int nt = 0; nt < 4; nt++) {
                int col = bn + warp_n * 32 + nt * 8 + (lane & 3) * 2;
                float2 zA = *(const float2*)(aux1 + (size_t)r0 * HXs + col);
                float2 zB = *(const float2*)(aux1 + (size_t)(r0 + 8) * HXs + col);
                float h0 = fmaxf(zA.x, 0.f) + gsA * zA.x + acc[mt][nt][0];
                float h1 = fmaxf(zA.y, 0.f) + gsA * zA.y + acc[mt][nt][1];
                float h2 = fmaxf(zB.x, 0.f) + gsB * zB.x + acc[mt][nt][2];
                float h3 = fmaxf(zB.y, 0.f) + gsB * zB.y + acc[mt][nt][3];
                __nv_bfloat162 loA, loB;
                __nv_bfloat162 hiA2 = split_hi2(h0, h1, loA);
                __nv_bfloat162 hiB2 = split_hi2(h2, h3, loB);
                *(__nv_bfloat162*)(a2o + (size_t)r0 * 2 * Ff + col)            = hiA2;
                *(__nv_bfloat162*)(a2o + (size_t)r0 * 2 * Ff + Ff + col)       = loA;
                *(__nv_bfloat162*)(a2o + (size_t)(r0 + 8) * 2 * Ff + col)      = hiB2;
                *(__nv_bfloat162*)(a2o + (size_t)(r0 + 8) * 2 * Ff + Ff + col) = loB;
            }
        }
    } else {
        #pragma unroll
        for (int mt = 0; mt < 4; mt++) {
            int r0 = bm + warp_m * 64 + mt * 16 + (lane >> 2);
            float gsA = 1.f + g_gp[r0] + g_gp[Tn + r0];
            float gsB = 1.f + g_gp[r0 + 8] + g_gp[Tn + r0 + 8];
            #pragma unroll
            for (int nt = 0; nt < 4; nt++) {
                int col = bn + warp_n * 32 + nt * 8 + (lane & 3) * 2;
                float2 wA = *(const float2*)(aux2 + (size_t)r0 * WXs + col);
                float2 wB = *(const float2*)(aux2 + (size_t)(r0 + 8) * WXs + col);
                float2 xA = *(const float2*)(aux1 + (size_t)r0 * Dd + col);
                float2 xB = *(const float2*)(aux1 + (size_t)(r0 + 8) * Dd + col);
                *(float2*)(C + (size_t)r0 * Dd + col) = make_float2(
                    xA.x + gsA * wA.x + acc[mt][nt][0], xA.y + gsA * wA.y + acc[mt][nt][1]);
                *(float2*)(C + (size_t)(r0 + 8) * Dd + col) = make_float2(
                    xB.x + gsB * wB.x + acc[mt][nt][2], xB.y + gsB * wB.y + acc[mt][nt][3]);
            }
        }
    }
}

// ---------------- RMS norm (+ split-bf16 A1 build + accumulator init fold) ------------
__global__ __launch_bounds__(256) void k_rms(const float* __restrict__ x,
                                             const float* __restrict__ lnw) {
    if (blockIdx.x == 0) {
        if (threadIdx.x < Bbat * Ee) g_dp[threadIdx.x] = 0.f;
        if (threadIdx.x == 0) g_zl = 0.f;
    }
    int t = blockIdx.x;
    const float* xr = x + (size_t)t * Dd;
    float s = 0.f;
    for (int d = threadIdx.x; d < Dd; d += 256) { float v = xr[d]; s += v * v; }
    __shared__ float red[256];
    red[threadIdx.x] = s; __syncthreads();
    for (int o = 128; o > 0; o >>= 1) {
        if (threadIdx.x < o) red[threadIdx.x] += red[threadIdx.x + o];
        __syncthreads();
    }
    float inv = rsqrtf(red[0] / (float)Dd + 1e-6f);
    __nv_bfloat16* a1 = g_A1 + (size_t)t * 2 * Dd;
    for (int d = threadIdx.x; d < Dd; d += 256) {
        float v = xr[d] * inv * lnw[d];
        g_wi[(size_t)t * Dd + d] = v;
        __nv_bfloat16 hi = __float2bfloat16(v);
        __nv_bfloat16 lo = __float2bfloat16(v - __bfloat162float(hi));
        a1[d] = hi; a1[Dd + d] = lo;
    }
}

// ---------------- B1x build: rows 0..3071 = Wi, rows 3072.. = Ai cols ----------------
__global__ __launch_bounds__(256) void k_splitB1x(const float* __restrict__ Wi,
                                                  const float* __restrict__ Ai) {
    int n = blockIdx.x;
    __nv_bfloat16* b = g_B1x + (size_t)n * 2 * Dd;
    if (n < Ff) {
        const float* wr = Wi + (size_t)n * Dd;
        for (int d = threadIdx.x; d < Dd; d += 256) {
            float v = wr[d];
            __nv_bfloat16 hi = __float2bfloat16(v);
            b[d] = hi; b[Dd + d] = __float2bfloat16(v - __bfloat162float(hi));
        }
    } else {
        int c = n - Ff, e = c >> 4, r = c & 15;
        const float* Ae = Ai + (size_t)e * Dd * 16 + r;
        for (int d = threadIdx.x; d < Dd; d += 256) {
            float v = Ae[d * 16];
            __nv_bfloat16 hi = __float2bfloat16(v);
            b[d] = hi; b[Dd + d] = __float2bfloat16(v - __bfloat162float(hi));
        }
    }
}

// ---------------- B2x build: rows 0..767 = Wo, rows 768.. = Ao cols ----------------
__global__ __launch_bounds__(256) void k_splitB2x(const float* __restrict__ Wo,
                                                  const float* __restrict__ Ao) {
    int n = blockIdx.x;
    __nv_bfloat16* b = g_B2x + (size_t)n * 2 * Ff;
    if (n < Dd) {
        const float* wr = Wo + (size_t)n * Ff;
        for (int f = threadIdx.x; f < Ff; f += 256) {
            float v = wr[f];
            __nv_bfloat16 hi = __float2bfloat16(v);
            b[f] = hi; b[Ff + f] = __float2bfloat16(v - __bfloat162float(hi));
        }
    } else {
        int c = n - Dd, e = c >> 4, r = c & 15;
        const float* Ae = Ao + (size_t)e * Ff * 16 + r;
        for (int f = threadIdx.x; f < Ff; f += 256) {
            float v = Ae[f * 16];
            __nv_bfloat16 hi = __float2bfloat16(v);
            b[f] = hi; b[Ff + f] = __float2bfloat16(v - __bfloat162float(hi));
        }
    }
}

// ---------------- Bd1 build: row f, col c=(e*16+r) -> Bi[e,r,f] ----------------
__global__ __launch_bounds__(256) void k_splitBd1(const float* __restrict__ Bi) {
    int f = blockIdx.x;
    __nv_bfloat16* b = g_Bd1 + (size_t)f * 512;
    for (int c = threadIdx.x; c < 256; c += 256) {
        int e = c >> 4, r = c & 15;
        float v = Bi[(size_t)e * 16 * Ff + (size_t)r * Ff + f];
        __nv_bfloat16 hi = __float2bfloat16(v);
        b[c] = hi; b[256 + c] = __float2bfloat16(v - __bfloat162float(hi));
    }
}
// ---------------- Bd2 build: row d, col c=(e*16+r) -> Bo[e,r,d] ----------------
__global__ __launch_bounds__(256) void k_splitBd2(const float* __restrict__ Bo) {
    int d = blockIdx.x;
    __nv_bfloat16* b = g_Bd2 + (size_t)d * 512;
    for (int c = threadIdx.x; c < 256; c += 256) {
        int e = c >> 4, r = c & 15;
        float v = Bo[(size_t)e * 16 * Dd + (size_t)r * Dd + d];
        __nv_bfloat16 hi = __float2bfloat16(v);
        b[c] = hi; b[256 + c] = __float2bfloat16(v - __bfloat162float(hi));
    }
}

// ---------------- logits = wi_in @ Wg^T (float4 smem) ----------------
__global__ __launch_bounds__(256) void k_logits(const float* __restrict__ Wg,
                                                float* __restrict__ out) {
    __shared__ float4 sWg[(Dd / 4) * 16];
    for (int i = threadIdx.x; i < Dd * 16 / 4; i += 256) {
        int d4 = i / 16, e = i % 16;
        const float* w = Wg + (size_t)e * Dd + d4 * 4;
        sWg[d4 * 16 + e] = make_float4(w[0], w[1], w[2], w[3]);
    }
    __syncthreads();
    int tok = blockIdx.x * 16 + (threadIdx.x >> 4);
    int e = threadIdx.x & 15;
    const float4* wr = (const float4*)(g_wi + (size_t)tok * Dd);
    float s = 0.f;
    #pragma unroll 4
    for (int d4 = 0; d4 < Dd / 4; d4++) {
        float4 xv = wr[d4];
        float4 wv = sWg[d4 * 16 + e];
        s += xv.x * wv.x + xv.y * wv.y + xv.z * wv.z + xv.w * wv.w;
    }
    out[OFF_LOGITS + (size_t)tok * 16 + e] = s;
}

// ---------------- softmax / top2 / gates / aux partials ----------------
__global__ __launch_bounds__(256) void k_gate(const float* __restrict__ rp,
                                              float* __restrict__ out) {
    int t = blockIdx.x * 256 + threadIdx.x;
    int lane = threadIdx.x & 31;
    const float* lg = out + OFF_LOGITS + (size_t)t * 16;
    float l[16];
    float mx = -1e30f;
    #pragma unroll
    for (int e = 0; e < 16; e++) { l[e] = lg[e]; mx = fmaxf(mx, l[e]); }
    float se = 0.f;
    #pragma unroll
    for (int e = 0; e < 16; e++) se += __expf(l[e] - mx);
    float lse = mx + __logf(se);
    out[OFF_ENERGY + t] = -lse;

    int e0 = 0; float b0 = l[0];
    #pragma unroll
    for (int e = 1; e < 16; e++) if (l[e] > b0) { b0 = l[e]; e0 = e; }
    int e1 = -1; float b1 = -1e30f;
    #pragma unroll
    for (int e = 0; e < 16; e++) if (e != e0 && l[e] > b1) { b1 = l[e]; e1 = e; }
    float v0 = __expf(b0 - lse), v1 = __expf(b1 - lse);
    float den = v0 + v1; if (den < 1e-9f) den = 1e-9f;
    float G0 = v0 / den, G1 = v1 / den;
    g_e[t] = e0; g_e[Tn + t] = e1;
    g_gate[t] = G0; g_gate[Tn + t] = G1;
    g_sh1[t] = (rp[Tn + t] < G1 * 5.0f) ? 1 : 0;

    int b = t >> 11;
    float zv = lse * lse;
    #pragma unroll
    for (int o = 16; o > 0; o >>= 1) zv += __shfl_xor_sync(0xffffffffu, zv, o);
    if (lane == 0) atomicAdd(&g_zl, zv);
    #pragma unroll
    for (int e = 0; e < 16; e++) {
        float pv = __expf(l[e] - lse);
        #pragma unroll
        for (int o = 16; o > 0; o >>= 1) pv += __shfl_xor_sync(0xffffffffu, pv, o);
        if (lane == 0) atomicAdd(&g_dp[b * 16 + e], pv);
    }
}

// ---------------- capacity scan ----------------
__global__ void k_scan(float* __restrict__ out) {
    if (threadIdx.x != 0) return;
    int b = blockIdx.x;
    int base = b * Nseq;
    int c0[16];
    #pragma unroll
    for (int e = 0; e < 16; e++) c0[e] = 0;
    for (int n = 0; n < Nseq; n++) {
        int t = base + n;
        int e = g_e[t];
        int pos = c0[e]++;
        bool s = pos < CAPc;
        g_gp[t] = s ? g_gate[t] : 0.f;
        out[OFF_GIDX + t] = s ? (float)e : 0.f;
    }
    int c1[16];
    #pragma unroll
    for (int e = 0; e < 16; e++) {
        int sv = c0[e] < CAPc ? c0[e] : CAPc;
        g_d1[b * 16 + e] = (float)sv / (float)Nseq;
        c1[e] = sv;
    }
    for (int n = 0; n < Nseq; n++) {
        int t = base + n;
        if (g_sh1[t]) {
            int e = g_e[Tn + t];
            int pos = c1[e]++;
            bool s = pos < CAPc;
            g_gp[Tn + t] = s ? g_gate[Tn + t] : 0.f;
            out[OFF_GIDX + Tn + t] = s ? (float)e : 0.f;
        } else {
            g_gp[Tn + t] = 0.f;
            out[OFF_GIDX + Tn + t] = 0.f;
        }
    }
}

// ---------------- aux scalars ----------------
__global__ void k_aux(float* __restrict__ out) {
    __shared__ float red[128];
    int i = threadIdx.x;
    red[i] = (g_dp[i] / (float)Nseq) * g_d1[i];
    __syncthreads();
    for (int o = 64; o > 0; o >>= 1) {
        if (i < o) red[i] += red[i + o];
        __syncthreads();
    }
    if (i == 0) {
        float bal = red[0] * 2.0f;
        float zl = g_zl / (float)Tn;
        out[OFF_BAL] = bal;
        out[OFF_ZL] = zl;
        out[OFF_AUX] = 0.01f * bal + 0.01f * zl;
    }
}

// ---------------- v1: gated u1 -> split bf16 [Tn x 256] ----------------
__global__ __launch_bounds__(256) void k_v1() {
    int base = blockIdx.x * 16;
    for (int i = threadIdx.x; i < 16 * 256; i += 256) {
        int tl = base + (i >> 8);
        int c = i & 255;
        int e = c >> 4;
        float g = (e == g_e[tl]) ? g_gp[tl] : (e == g_e[Tn + tl]) ? g_gp[Tn + tl] : 0.f;
        float v = 2.f * g * g_hx[(size_t)tl * HXs + Ff + c];
        __nv_bfloat16 hi = __float2bfloat16(v);
        g_V1[(size_t)tl * 512 + c] = hi;
        g_V1[(size_t)tl * 512 + 256 + c] = __float2bfloat16(v - __bfloat162float(hi));
    }
}

// ---------------- v2: gated u2 -> split bf16 [Tn x 256] ----------------
__global__ __launch_bounds__(256) void k_v2() {
    int base = blockIdx.x * 16;
    for (int i = threadIdx.x; i < 16 * 256; i += 256) {
        int tl = base + (i >> 8);
        int c = i & 255;
        int e = c >> 4;
        float g = (e == g_e[tl]) ? g_gp[tl] : (e == g_e[Tn + tl]) ? g_gp[Tn + tl] : 0.f;
        float v = 2.f * g * g_wx[(size_t)tl * WXs + Dd + c];
        __nv_bfloat16 hi = __float2bfloat16(v);
        g_V2[(size_t)tl * 512 + c] = hi;
        g_V2[(size_t)tl * 512 + 256 + c] = __float2bfloat16(v - __bfloat162float(hi));
    }
}

// ---------------- launch ----------------
extern "C" void kernel_launch(void* const* d_in, const int* in_sizes, int n_in,
                              void* d_out, int out_size) {
    const float* x   = (const float*)d_in[0];
    const float* rp  = (const float*)d_in[1];
    const float* lnw = (const float*)d_in[2];
    const float* Wg  = (const float*)d_in[3];
    const float* Wi  = (const float*)d_in[4];
    const float* Wo  = (const float*)d_in[5];
    const float* Ai  = (const float*)d_in[6];
    const float* Bi  = (const float*)d_in[7];
    const float* Ao  = (const float*)d_in[8];
    const float* Bo  = (const float*)d_in[9];
    float* out = (float*)d_out;

    cudaFuncSetAttribute(k_tc_gemm, cudaFuncAttributeMaxDynamicSharedMemorySize, SMEM_GEMM);

    __nv_bfloat16 *A1p, *B1xp, *A2p, *B2xp, *V1p, *V2p, *Bd1p, *Bd2p;
    float *hxp, *wxp;
    cudaGetSymbolAddress((void**)&A1p,  g_A1);
    cudaGetSymbolAddress((void**)&B1xp, g_B1x);
    cudaGetSymbolAddress((void**)&A2p,  g_A2);
    cudaGetSymbolAddress((void**)&B2xp, g_B2x);
    cudaGetSymbolAddress((void**)&V1p,  g_V1);
    cudaGetSymbolAddress((void**)&V2p,  g_V2);
    cudaGetSymbolAddress((void**)&Bd1p, g_Bd1);
    cudaGetSymbolAddress((void**)&Bd2p, g_Bd2);
    cudaGetSymbolAddress((void**)&hxp,  g_hx);
    cudaGetSymbolAddress((void**)&wxp,  g_wx);

    // prep
    k_rms<<<Tn, 256>>>(x, lnw);                          // #1
    k_splitB1x<<<N1X, 256>>>(Wi, Ai);                    // #2
    k_splitB2x<<<N2X, 256>>>(Wo, Ao);                    // #3
    // GEMM1: [z | u1all] = A1 @ B1x^T    (ncu slot #4)
    k_tc_gemm<<<dim3(N1X / 128, Tn / 128), 256, SMEM_GEMM>>>(
        A1p, B1xp, hxp, N1X, Dd, Dd / 64, 3 * Dd / 64, 0, nullptr, nullptr, nullptr);
    k_splitBd1<<<Ff, 256>>>(Bi);
    k_splitBd2<<<Dd, 256>>>(Bo);
    // gating chain
    k_logits<<<Tn / 16, 256>>>(Wg, out);
    k_gate<<<Tn / 256, 256>>>(rp, out);
    k_scan<<<Bbat, 32>>>(out);
    k_aux<<<1, 128>>>(out);
    // wi-path delta GEMM with fused h-epilogue -> A2
    k_v1<<<Tn / 16, 256>>>();
    k_tc_gemm<<<dim3(Ff / 128, Tn / 128), 256, SMEM_GEMM>>>(
        V1p, Bd1p, nullptr, Ff, 256, 4, 12, 1, hxp, nullptr, A2p);
    // GEMM2: [w | u2all] = A2 @ B2x^T
    k_tc_gemm<<<dim3(N2X / 128, Tn / 128), 256, SMEM_GEMM>>>(
        A2p, B2xp, wxp, N2X, Ff, Ff / 64, 3 * Ff / 64, 0, nullptr, nullptr, nullptr);
    // wo-path delta GEMM with fused out-epilogue
    k_v2<<<Tn / 16, 256>>>();
    k_tc_gemm<<<dim3(Dd / 128, Tn / 128), 256, SMEM_GEMM>>>(
        V2p, Bd2p, out, Dd, 256, 4, 12, 2, x, wxp, nullptr);
}

// round 15
// speedup vs baseline: 1.8991x; 1.1193x over previous
#include <cuda_runtime.h>
#include <cuda_bf16.h>
#include <math.h>
#include <stdint.h>

// Problem constants
#define Tn 16384            // B*N tokens
#define Dd 768
#define Ff 3072
#define Ee 16
#define CAPc 160
#define Bbat 8
#define Nseq 2048

#define N1X 3328            // GEMM1 N: 3072 z + 256 u1
#define N2X 1024            // GEMM2 N: 768 w + 256 u2
#define HXs 3328            // g_hx row stride
#define WXs 1024            // g_wx row stride

// Output layout (float32, concatenated in reference return order)
#define OFF_AUX    12582912
#define OFF_BAL    12582913
#define OFF_ZL     12582914
#define OFF_LOGITS 12582915ll
#define OFF_ENERGY 12845059ll
#define OFF_GIDX   12861443ll

// ---------------- scratch (device globals; no runtime allocation) ----------------
__device__ float g_wi[(size_t)Tn * Dd];                 // RMS-normed input (fp32)
__device__ float g_hx[(size_t)Tn * HXs];                // [z | u1_all] raw
__device__ float g_wx[(size_t)Tn * WXs];                // [w | u2_all] raw
__device__ __nv_bfloat16 g_A1 [(size_t)Tn * 2 * Dd];    // [wi_hi | wi_lo]
__device__ __nv_bfloat16 g_B1x[(size_t)N1X * 2 * Dd];   // [Wi|Ai rows, hi|lo]
__device__ __nv_bfloat16 g_A2 [(size_t)Tn * 2 * Ff];    // [h_hi | h_lo]
__device__ __nv_bfloat16 g_B2x[(size_t)N2X * 2 * Ff];   // [Wo|Ao rows, hi|lo]
__device__ __nv_bfloat16 g_V1 [(size_t)Tn * 512];       // gated u1 [hi|lo], K=256
__device__ __nv_bfloat16 g_V2 [(size_t)Tn * 512];       // gated u2 [hi|lo]
__device__ __nv_bfloat16 g_Bd1[(size_t)Ff * 512];       // Bi^T rows [hi|lo]
__device__ __nv_bfloat16 g_Bd2[(size_t)Dd * 512];       // Bo^T rows [hi|lo]
__device__ int   g_e  [2 * Tn];
__device__ float g_gate[2 * Tn];
__device__ float g_gp  [2 * Tn];                        // gate after drop (0 if dropped)
__device__ int   g_sh1 [Tn];
__device__ float g_dp[Bbat * Ee];
__device__ float g_d1[Bbat * Ee];
__device__ float g_zl;

// ---------------- PTX helpers (sm_100-safe) ----------------
__device__ __forceinline__ uint32_t s2u(const void* p) {
    uint32_t a;
    asm("{ .reg .u64 t; cvta.to.shared.u64 t, %1; cvt.u32.u64 %0, t; }" : "=r"(a) : "l"(p));
    return a;
}
__device__ __forceinline__ void cpa16(uint32_t s, const void* g) {
    asm volatile("cp.async.cg.shared.global [%0], [%1], 16;\n" :: "r"(s), "l"(g));
}
#define CPA_COMMIT() asm volatile("cp.async.commit_group;\n" ::: "memory")
#define CPA_WAIT1()  asm volatile("cp.async.wait_group 1;\n" ::: "memory")

__device__ __forceinline__ void ldsm4(uint32_t* r, uint32_t a) {
    asm volatile("ldmatrix.sync.aligned.m8n8.x4.shared.b16 {%0,%1,%2,%3}, [%4];"
                 : "=r"(r[0]), "=r"(r[1]), "=r"(r[2]), "=r"(r[3]) : "r"(a));
}
__device__ __forceinline__ void mma16816(float* c, const uint32_t* a, uint32_t b0, uint32_t b1) {
    asm volatile("mma.sync.aligned.m16n8k16.row.col.f32.bf16.bf16.f32 "
                 "{%0,%1,%2,%3}, {%4,%5,%6,%7}, {%8,%9}, {%0,%1,%2,%3};"
                 : "+f"(c[0]), "+f"(c[1]), "+f"(c[2]), "+f"(c[3])
                 : "r"(a[0]), "r"(a[1]), "r"(a[2]), "r"(a[3]), "r"(b0), "r"(b1));
}

#define SWZ(o) ((o) ^ (((o) >> 3) & 0x70))

// GEMM smem: A stages [128][64]bf16 = 16KB (x3), B stages [128][64]bf16 = 16KB (x3)
#define SMEM_GEMM 98304

__device__ __forceinline__ __nv_bfloat162 split_hi2(float a, float b,
                                                    __nv_bfloat162& lo) {
    __nv_bfloat162 hi;
    hi.x = __float2bfloat16(a); hi.y = __float2bfloat16(b);
    lo.x = __float2bfloat16(a - __bfloat162float(hi.x));
    lo.y = __float2bfloat16(b - __bfloat162float(hi.y));
    return hi;
}

// ---------------- mma.sync split-bf16 GEMM: C[m,n] = sum_k A[m,k]*B[n,k] ----------------
// Tile 128x128, K-chunk 64, 3-stage cp.async, 256 threads, 2 CTAs/SM, single sync/chunk.
// A terms: hi, lo, hi ; B terms: hi, hi, lo (3-term schedule over 2-term storage)
// Requires cpt >= 3 (chunks 0..2 are all in term 0).
// mode 0: raw store to C (stride Ncols)
// mode 1: h-epilogue: z=aux1 (stride HXs); h=relu(z)+gs*z+acc; write A2 [hi|lo] (a2o)
// mode 2: out-epilogue: out = aux1(x,768) + (1+gs)*aux2(w,WXs) + acc; store C (768)
__global__ __launch_bounds__(256, 2)
void k_tc_gemm(const __nv_bfloat16* __restrict__ A, const __nv_bfloat16* __restrict__ B,
               float* __restrict__ C, int Ncols, int K, int cpt, int KI, int mode,
               const float* __restrict__ aux1, const float* __restrict__ aux2,
               __nv_bfloat16* __restrict__ a2o) {
    extern __shared__ char smem[];
    const uint32_t sb = s2u(smem);
    const int tid = threadIdx.x;
    const int wid = tid >> 5;
    const int lane = tid & 31;
    const int warp_m = wid & 1;          // 2 groups of M=64
    const int warp_n = wid >> 1;         // 4 groups of N=32
    const int bm = blockIdx.y * 128;
    const int bn = blockIdx.x * 128;
    const int K2 = 2 * K;

    // ---- loader precompute: per-thread global pointers + swizzled smem offsets ----
    const __nv_bfloat16* agp[4];
    const __nv_bfloat16* bgp[4];
    uint32_t asm_[4], bsm_[4];
    #pragma unroll
    for (int j = 0; j < 4; j++) {
        int idx = tid + 256 * j, row = idx >> 3, seg = idx & 7;
        agp[j] = A + (size_t)(bm + row) * K2 + seg * 8;
        bgp[j] = B + (size_t)(bn + row) * K2 + seg * 8;
        uint32_t so = SWZ(row * 128 + seg * 16);
        asm_[j] = sb + so;
        bsm_[j] = sb + 49152 + so;
    }

    // ---- compute precompute: row offsets + swizzle XOR masks (row-only dependent) ----
    const uint32_t hiA = (lane >> 4) << 4;
    const uint32_t hiB = ((lane >> 3) & 1) << 4;
    uint32_t aro[4], axm[4];
    #pragma unroll
    for (int mt = 0; mt < 4; mt++) {
        int row = warp_m * 64 + mt * 16 + (lane & 15);
        aro[mt] = row * 128;
        axm[mt] = (row & 7) << 4;
    }
    uint32_t bro[2], bxm[2];
    #pragma unroll
    for (int g = 0; g < 2; g++) {
        int nr = warp_n * 32 + g * 16 + ((lane >> 4) << 3) + (lane & 7);
        bro[g] = nr * 128;
        bxm[g] = (nr & 7) << 4;
    }

    float acc[4][4][4];
    #pragma unroll
    for (int i = 0; i < 4; i++)
        #pragma unroll
        for (int j = 0; j < 4; j++)
            #pragma unroll
            for (int q = 0; q < 4; q++) acc[i][j][q] = 0.f;

    // prologue: chunks 0,1 (term 0, k-offsets 0 and 64; cpt >= 3 guarantees term 0)
    #pragma unroll
    for (int c = 0; c < 2; c++) {
        #pragma unroll
        for (int j = 0; j < 4; j++) cpa16(asm_[j] + c * 16384, agp[j] + c * 64);
        #pragma unroll
        for (int j = 0; j < 4; j++) cpa16(bsm_[j] + c * 16384, bgp[j] + c * 64);
        CPA_COMMIT();
    }

    // incremental chunk state (no division in the loop)
    int si = 0;            // compute stage for chunk i
    int sj = 2;            // prefetch stage for chunk i+2
    int tj = 0, kcj = 128; // (term, k-offset) of chunk 2  [cpt >= 3]

    for (int i = 0; i < KI; i++) {
        CPA_WAIT1();
        __syncthreads();

        if (i + 2 < KI) {
            int goA = (tj == 1 ? K : 0) + kcj;
            int goB = (tj == 2 ? K : 0) + kcj;
            uint32_t soff = sj * 16384;
            #pragma unroll
            for (int jj = 0; jj < 4; jj++) cpa16(asm_[jj] + soff, agp[jj] + goA);
            #pragma unroll
            for (int jj = 0; jj < 4; jj++) cpa16(bsm_[jj] + soff, bgp[jj] + goB);
            kcj += 64;
            if (kcj == K) { kcj = 0; tj++; }
            sj = (sj == 2) ? 0 : sj + 1;
        }
        CPA_COMMIT();

        // per-chunk stage bases
        const uint32_t sbase = si * 16384;
        uint32_t saA[4], sBb[2];
        #pragma unroll
        for (int mt = 0; mt < 4; mt++) saA[mt] = sb + sbase + aro[mt];
        #pragma unroll
        for (int g = 0; g < 2; g++) sBb[g] = sb + 49152 + sbase + bro[g];
        si = (si == 2) ? 0 : si + 1;

        #pragma unroll
        for (int ks = 0; ks < 4; ks++) {
            uint32_t a[4][4];
            #pragma unroll
            for (int mt = 0; mt < 4; mt++)
                ldsm4(a[mt], saA[mt] + ((ks * 32 + hiA) ^ axm[mt]));
            uint32_t b[2][4];
            #pragma unroll
            for (int g = 0; g < 2; g++)
                ldsm4(b[g], sBb[g] + ((ks * 32 + hiB) ^ bxm[g]));
            #pragma unroll
            for (int mt = 0; mt < 4; mt++)
                #pragma unroll
                for (int nt = 0; nt < 4; nt++) {
                    int g = nt >> 1, hf = (nt & 1) << 1;
                    mma16816(acc[mt][nt], a[mt], b[g][hf], b[g][hf + 1]);
                }
        }
        // no trailing sync: next iteration's top sync orders this compute
        // before any thread's prefetch overwrites this stage.
    }

    if (mode == 0) {
        #pragma unroll
        for (int mt = 0; mt < 4; mt++) {
            int r0 = bm + warp_m * 64 + mt * 16 + (lane >> 2);
            #pragma unroll
            for (int nt = 0; nt < 4; nt++) {
                int col = bn + warp_n * 32 + nt * 8 + (lane & 3) * 2;
                *(float2*)(C + (size_t)r0 * Ncols + col)       = make_float2(acc[mt][nt][0], acc[mt][nt][1]);
                *(float2*)(C + (size_t)(r0 + 8) * Ncols + col) = make_float2(acc[mt][nt][2], acc[mt][nt][3]);
            }
        }
    } else if (mode == 1) {
        #pragma unroll
        for (int mt = 0; mt < 4; mt++) {
            int r0 = bm + warp_m * 64 + mt * 16 + (lane >> 2);
            float gsA = g_gp[r0] + g_gp[Tn + r0];
            float gsB = g_gp[r0 + 8] + g_gp[Tn + r0 + 8];
            #pragma unroll
            for (int nt = 0; nt < 4; nt++) {
                int col = bn + warp_n * 32 + nt * 8 + (lane & 3) * 2;
                float2 zA = *(const float2*)(aux1 + (size_t)r0 * HXs + col);
                float2 zB = *(const float2*)(aux1 + (size_t)(r0 + 8) * HXs + col);
                float h0 = fmaxf(zA.x, 0.f) + gsA * zA.x + acc[mt][nt][0];
                float h1 = fmaxf(zA.y, 0.f) + gsA * zA.y + acc[mt][nt][1];
                float h2 = fmaxf(zB.x, 0.f) + gsB * zB.x + acc[mt][nt][2];
                float h3 = fmaxf(zB.y, 0.f) + gsB * zB.y + acc[mt][nt][3];
                __nv_bfloat162 loA, loB;
                __nv_bfloat162 hiA2 = split_hi2(h0, h1, loA);
                __nv_bfloat162 hiB2 = split_hi2(h2, h3, loB);
                *(__nv_bfloat162*)(a2o + (size_t)r0 * 2 * Ff + col)            = hiA2;
                *(__nv_bfloat162*)(a2o + (size_t)r0 * 2 * Ff + Ff + col)       = loA;
                *(__nv_bfloat162*)(a2o + (size_t)(r0 + 8) * 2 * Ff + col)      = hiB2;
                *(__nv_bfloat162*)(a2o + (size_t)(r0 + 8) * 2 * Ff + Ff + col) = loB;
            }
        }
    } else {
        #pragma unroll
        for (int mt = 0; mt < 4; mt++) {
            int r0 = bm + warp_m * 64 + mt * 16 + (lane >> 2);
            float gsA = 1.f + g_gp[r0] + g_gp[Tn + r0];
            float gsB = 1.f + g_gp[r0 + 8] + g_gp[Tn + r0 + 8];
            #pragma unroll
            for (int nt = 0; nt < 4; nt++) {
                int col = bn + warp_n * 32 + nt * 8 + (lane & 3) * 2;
                float2 wA = *(const float2*)(aux2 + (size_t)r0 * WXs + col);
                float2 wB = *(const float2*)(aux2 + (size_t)(r0 + 8) * WXs + col);
                float2 xA = *(const float2*)(aux1 + (size_t)r0 * Dd + col);
                float2 xB = *(const float2*)(aux1 + (size_t)(r0 + 8) * Dd + col);
                *(float2*)(C + (size_t)r0 * Dd + col) = make_float2(
                    xA.x + gsA * wA.x + acc[mt][nt][0], xA.y + gsA * wA.y + acc[mt][nt][1]);
                *(float2*)(C + (size_t)(r0 + 8) * Dd + col) = make_float2(
                    xB.x + gsB * wB.x + acc[mt][nt][2], xB.y + gsB * wB.y + acc[mt][nt][3]);
            }
        }
    }
}

// ---------------- RMS norm (+ split-bf16 A1 build + accumulator init fold) ------------
__global__ __launch_bounds__(256) void k_rms(const float* __restrict__ x,
                                             const float* __restrict__ lnw) {
    if (blockIdx.x == 0) {
        if (threadIdx.x < Bbat * Ee) g_dp[threadIdx.x] = 0.f;
        if (threadIdx.x == 0) g_zl = 0.f;
    }
    int t = blockIdx.x;
    const float* xr = x + (size_t)t * Dd;
    float s = 0.f;
    for (int d = threadIdx.x; d < Dd; d += 256) { float v = xr[d]; s += v * v; }
    __shared__ float red[256];
    red[threadIdx.x] = s; __syncthreads();
    for (int o = 128; o > 0; o >>= 1) {
        if (threadIdx.x < o) red[threadIdx.x] += red[threadIdx.x + o];
        __syncthreads();
    }
    float inv = rsqrtf(red[0] / (float)Dd + 1e-6f);
    __nv_bfloat16* a1 = g_A1 + (size_t)t * 2 * Dd;
    for (int d = threadIdx.x; d < Dd; d += 256) {
        float v = xr[d] * inv * lnw[d];
        g_wi[(size_t)t * Dd + d] = v;
        __nv_bfloat16 hi = __float2bfloat16(v);
        __nv_bfloat16 lo = __float2bfloat16(v - __bfloat162float(hi));
        a1[d] = hi; a1[Dd + d] = lo;
    }
}

// ---------------- B1x build: rows 0..3071 = Wi, rows 3072.. = Ai cols ----------------
__global__ __launch_bounds__(256) void k_splitB1x(const float* __restrict__ Wi,
                                                  const float* __restrict__ Ai) {
    int n = blockIdx.x;
    __nv_bfloat16* b = g_B1x + (size_t)n * 2 * Dd;
    if (n < Ff) {
        const float* wr = Wi + (size_t)n * Dd;
        for (int d = threadIdx.x; d < Dd; d += 256) {
            float v = wr[d];
            __nv_bfloat16 hi = __float2bfloat16(v);
            b[d] = hi; b[Dd + d] = __float2bfloat16(v - __bfloat162float(hi));
        }
    } else {
        int c = n - Ff, e = c >> 4, r = c & 15;
        const float* Ae = Ai + (size_t)e * Dd * 16 + r;
        for (int d = threadIdx.x; d < Dd; d += 256) {
            float v = Ae[d * 16];
            __nv_bfloat16 hi = __float2bfloat16(v);
            b[d] = hi; b[Dd + d] = __float2bfloat16(v - __bfloat162float(hi));
        }
    }
}

// ---------------- B2x build: rows 0..767 = Wo, rows 768.. = Ao cols ----------------
__global__ __launch_bounds__(256) void k_splitB2x(const float* __restrict__ Wo,
                                                  const float* __restrict__ Ao) {
    int n = blockIdx.x;
    __nv_bfloat16* b = g_B2x + (size_t)n * 2 * Ff;
    if (n < Dd) {
        const float* wr = Wo + (size_t)n * Ff;
        for (int f = threadIdx.x; f < Ff; f += 256) {
            float v = wr[f];
            __nv_bfloat16 hi = __float2bfloat16(v);
            b[f] = hi; b[Ff + f] = __float2bfloat16(v - __bfloat162float(hi));
        }
    } else {
        int c = n - Dd, e = c >> 4, r = c & 15;
        const float* Ae = Ao + (size_t)e * Ff * 16 + r;
        for (int f = threadIdx.x; f < Ff; f += 256) {
            float v = Ae[f * 16];
            __nv_bfloat16 hi = __float2bfloat16(v);
            b[f] = hi; b[Ff + f] = __float2bfloat16(v - __bfloat162float(hi));
        }
    }
}

// ---------------- Bd1 build: row f, col c=(e*16+r) -> Bi[e,r,f] ----------------
__global__ __launch_bounds__(256) void k_splitBd1(const float* __restrict__ Bi) {
    int f = blockIdx.x;
    __nv_bfloat16* b = g_Bd1 + (size_t)f * 512;
    for (int c = threadIdx.x; c < 256; c += 256) {
        int e = c >> 4, r = c & 15;
        float v = Bi[(size_t)e * 16 * Ff + (size_t)r * Ff + f];
        __nv_bfloat16 hi = __float2bfloat16(v);
        b[c] = hi; b[256 + c] = __float2bfloat16(v - __bfloat162float(hi));
    }
}
// ---------------- Bd2 build: row d, col c=(e*16+r) -> Bo[e,r,d] ----------------
__global__ __launch_bounds__(256) void k_splitBd2(const float* __restrict__ Bo) {
    int d = blockIdx.x;
    __nv_bfloat16* b = g_Bd2 + (size_t)d * 512;
    for (int c = threadIdx.x; c < 256; c += 256) {
        int e = c >> 4, r = c & 15;
        float v = Bo[(size_t)e * 16 * Dd + (size_t)r * Dd + d];
        __nv_bfloat16 hi = __float2bfloat16(v);
        b[c] = hi; b[256 + c] = __float2bfloat16(v - __bfloat162float(hi));
    }
}

// ---------------- logits = wi_in @ Wg^T (float4 smem) ----------------
__global__ __launch_bounds__(256) void k_logits(const float* __restrict__ Wg,
                                                float* __restrict__ out) {
    __shared__ float4 sWg[(Dd / 4) * 16];
    for (int i = threadIdx.x; i < Dd * 16 / 4; i += 256) {
        int d4 = i / 16, e = i % 16;
        const float* w = Wg + (size_t)e * Dd + d4 * 4;
        sWg[d4 * 16 + e] = make_float4(w[0], w[1], w[2], w[3]);
    }
    __syncthreads();
    int tok = blockIdx.x * 16 + (threadIdx.x >> 4);
    int e = threadIdx.x & 15;
    const float4* wr = (const float4*)(g_wi + (size_t)tok * Dd);
    float s = 0.f;
    #pragma unroll 4
    for (int d4 = 0; d4 < Dd / 4; d4++) {
        float4 xv = wr[d4];
        float4 wv = sWg[d4 * 16 + e];
        s += xv.x * wv.x + xv.y * wv.y + xv.z * wv.z + xv.w * wv.w;
    }
    out[OFF_LOGITS + (size_t)tok * 16 + e] = s;
}

// ---------------- softmax / top2 / gates / aux partials ----------------
__global__ __launch_bounds__(256) void k_gate(const float* __restrict__ rp,
                                              float* __restrict__ out) {
    int t = blockIdx.x * 256 + threadIdx.x;
    int lane = threadIdx.x & 31;
    const float* lg = out + OFF_LOGITS + (size_t)t * 16;
    float l[16];
    float mx = -1e30f;
    #pragma unroll
    for (int e = 0; e < 16; e++) { l[e] = lg[e]; mx = fmaxf(mx, l[e]); }
    float se = 0.f;
    #pragma unroll
    for (int e = 0; e < 16; e++) se += __expf(l[e] - mx);
    float lse = mx + __logf(se);
    out[OFF_ENERGY + t] = -lse;

    int e0 = 0; float b0 = l[0];
    #pragma unroll
    for (int e = 1; e < 16; e++) if (l[e] > b0) { b0 = l[e]; e0 = e; }
    int e1 = -1; float b1 = -1e30f;
    #pragma unroll
    for (int e = 0; e < 16; e++) if (e != e0 && l[e] > b1) { b1 = l[e]; e1 = e; }
    float v0 = __expf(b0 - lse), v1 = __expf(b1 - lse);
    float den = v0 + v1; if (den < 1e-9f) den = 1e-9f;
    float G0 = v0 / den, G1 = v1 / den;
    g_e[t] = e0; g_e[Tn + t] = e1;
    g_gate[t] = G0; g_gate[Tn + t] = G1;
    g_sh1[t] = (rp[Tn + t] < G1 * 5.0f) ? 1 : 0;

    int b = t >> 11;
    float zv = lse * lse;
    #pragma unroll
    for (int o = 16; o > 0; o >>= 1) zv += __shfl_xor_sync(0xffffffffu, zv, o);
    if (lane == 0) atomicAdd(&g_zl, zv);
    #pragma unroll
    for (int e = 0; e < 16; e++) {
        float pv = __expf(l[e] - lse);
        #pragma unroll
        for (int o = 16; o > 0; o >>= 1) pv += __shfl_xor_sync(0xffffffffu, pv, o);
        if (lane == 0) atomicAdd(&g_dp[b * 16 + e], pv);
    }
}

// ---------------- capacity scan: 16 threads per batch, thread e owns expert e --------
__global__ void k_scan(float* __restrict__ out) {
    int b = blockIdx.x;
    int e = threadIdx.x;            // 0..15
    int base = b * Nseq;
    int cnt = 0;
    for (int n = 0; n < Nseq; n += 4) {
        int4 ev = *(const int4*)(g_e + base + n);
        #pragma unroll
        for (int j = 0; j < 4; j++) {
            int et = (j == 0) ? ev.x : (j == 1) ? ev.y : (j == 2) ? ev.z : ev.w;
            if (et == e) {
                int t = base + n + j;
                bool s = cnt < CAPc;
                cnt++;
                g_gp[t] = s ? g_gate[t] : 0.f;
                out[OFF_GIDX + t] = s ? (float)e : 0.f;
            }
        }
    }
    int sv = cnt < CAPc ? cnt : CAPc;
    g_d1[b * 16 + e] = (float)sv / (float)Nseq;
    int cnt1 = sv;
    for (int n = 0; n < Nseq; n += 4) {
        int4 ev = *(const int4*)(g_e + Tn + base + n);
        int4 sh = *(const int4*)(g_sh1 + base + n);
        #pragma unroll
        for (int j = 0; j < 4; j++) {
            int et = (j == 0) ? ev.x : (j == 1) ? ev.y : (j == 2) ? ev.z : ev.w;
            int sj = (j == 0) ? sh.x : (j == 1) ? sh.y : (j == 2) ? sh.z : sh.w;
            if (et == e) {
                int t = base + n + j;
                if (sj) {
                    bool s = cnt1 < CAPc;
                    cnt1++;
                    g_gp[Tn + t] = s ? g_gate[Tn + t] : 0.f;
                    out[OFF_GIDX + Tn + t] = s ? (float)e : 0.f;
                } else {
                    g_gp[Tn + t] = 0.f;
                    out[OFF_GIDX + Tn + t] = 0.f;
                }
            }
        }
    }
}

// ---------------- aux scalars ----------------
__global__ void k_aux(float* __restrict__ out) {
    __shared__ float red[128];
    int i = threadIdx.x;
    red[i] = (g_dp[i] / (float)Nseq) * g_d1[i];
    __syncthreads();
    for (int o = 64; o > 0; o >>= 1) {
        if (i < o) red[i] += red[i + o];
        __syncthreads();
    }
    if (i == 0) {
        float bal = red[0] * 2.0f;
        float zl = g_zl / (float)Tn;
        out[OFF_BAL] = bal;
        out[OFF_ZL] = zl;
        out[OFF_AUX] = 0.01f * bal + 0.01f * zl;
    }
}

// ---------------- v1: gated u1 -> split bf16 [Tn x 256] ----------------
__global__ __launch_bounds__(256) void k_v1() {
    int base = blockIdx.x * 16;
    for (int i = threadIdx.x; i < 16 * 256; i += 256) {
        int tl = base + (i >> 8);
        int c = i & 255;
        int e = c >> 4;
        float g = (e == g_e[tl]) ? g_gp[tl] : (e == g_e[Tn + tl]) ? g_gp[Tn + tl] : 0.f;
        float v = 2.f * g * g_hx[(size_t)tl * HXs + Ff + c];
        __nv_bfloat16 hi = __float2bfloat16(v);
        g_V1[(size_t)tl * 512 + c] = hi;
        g_V1[(size_t)tl * 512 + 256 + c] = __float2bfloat16(v - __bfloat162float(hi));
    }
}

// ---------------- v2: gated u2 -> split bf16 [Tn x 256] ----------------
__global__ __launch_bounds__(256) void k_v2() {
    int base = blockIdx.x * 16;
    for (int i = threadIdx.x; i < 16 * 256; i += 256) {
        int tl = base + (i >> 8);
        int c = i & 255;
        int e = c >> 4;
        float g = (e == g_e[tl]) ? g_gp[tl] : (e == g_e[Tn + tl]) ? g_gp[Tn + tl] : 0.f;
        float v = 2.f * g * g_wx[(size_t)tl * WXs + Dd + c];
        __nv_bfloat16 hi = __float2bfloat16(v);
        g_V2[(size_t)tl * 512 + c] = hi;
        g_V2[(size_t)tl * 512 + 256 + c] = __float2bfloat16(v - __bfloat162float(hi));
    }
}

// ---------------- launch ----------------
extern "C" void kernel_launch(void* const* d_in, const int* in_sizes, int n_in,
                              void* d_out, int out_size) {
    const float* x   = (const float*)d_in[0];
    const float* rp  = (const float*)d_in[1];
    const float* lnw = (const float*)d_in[2];
    const float* Wg  = (const float*)d_in[3];
    const float* Wi  = (const float*)d_in[4];
    const float* Wo  = (const float*)d_in[5];
    const float* Ai  = (const float*)d_in[6];
    const float* Bi  = (const float*)d_in[7];
    const float* Ao  = (const float*)d_in[8];
    const float* Bo  = (const float*)d_in[9];
    float* out = (float*)d_out;

    cudaFuncSetAttribute(k_tc_gemm, cudaFuncAttributeMaxDynamicSharedMemorySize, SMEM_GEMM);

    __nv_bfloat16 *A1p, *B1xp, *A2p, *B2xp, *V1p, *V2p, *Bd1p, *Bd2p;
    float *hxp, *wxp;
    cudaGetSymbolAddress((void**)&A1p,  g_A1);
    cudaGetSymbolAddress((void**)&B1xp, g_B1x);
    cudaGetSymbolAddress((void**)&A2p,  g_A2);
    cudaGetSymbolAddress((void**)&B2xp, g_B2x);
    cudaGetSymbolAddress((void**)&V1p,  g_V1);
    cudaGetSymbolAddress((void**)&V2p,  g_V2);
    cudaGetSymbolAddress((void**)&Bd1p, g_Bd1);
    cudaGetSymbolAddress((void**)&Bd2p, g_Bd2);
    cudaGetSymbolAddress((void**)&hxp,  g_hx);
    cudaGetSymbolAddress((void**)&wxp,  g_wx);

    // prep
    k_rms<<<Tn, 256>>>(x, lnw);                          // #1
    k_splitB1x<<<N1X, 256>>>(Wi, Ai);                    // #2
    k_splitB2x<<<N2X, 256>>>(Wo, Ao);                    // #3
    // GEMM1: [z | u1all] = A1 @ B1x^T    (ncu slot #4)
    k_tc_gemm<<<dim3(N1X / 128, Tn / 128), 256, SMEM_GEMM>>>(
        A1p, B1xp, hxp, N1X, Dd, Dd / 64, 3 * Dd / 64, 0, nullptr, nullptr, nullptr);
    k_splitBd1<<<Ff, 256>>>(Bi);
    k_splitBd2<<<Dd, 256>>>(Bo);
    // gating chain
    k_logits<<<Tn / 16, 256>>>(Wg, out);
    k_gate<<<Tn / 256, 256>>>(rp, out);
    k_scan<<<Bbat, 16>>>(out);
    k_aux<<<1, 128>>>(out);
    // wi-path delta GEMM with fused h-epilogue -> A2
    k_v1<<<Tn / 16, 256>>>();
    k_tc_gemm<<<dim3(Ff / 128, Tn / 128), 256, SMEM_GEMM>>>(
        V1p, Bd1p, nullptr, Ff, 256, 4, 12, 1, hxp, nullptr, A2p);
    // GEMM2: [w | u2all] = A2 @ B2x^T
    k_tc_gemm<<<dim3(N2X / 128, Tn / 128), 256, SMEM_GEMM>>>(
        A2p, B2xp, wxp, N2X, Ff, Ff / 64, 3 * Ff / 64, 0, nullptr, nullptr, nullptr);
    // wo-path delta GEMM with fused out-epilogue
    k_v2<<<Tn / 16, 256>>>();
    k_tc_gemm<<<dim3(Dd / 128, Tn / 128), 256, SMEM_GEMM>>>(
        V2p, Bd2p, out, Dd, 256, 4, 12, 2, x, wxp, nullptr);
}

// round 17
// speedup vs baseline: 3.4141x; 1.7977x over previous
#include <cuda_runtime.h>
#include <cuda_fp16.h>
#include <math.h>
#include <stdint.h>

// Problem constants
#define Tn 16384            // B*N tokens
#define Dd 768
#define Ff 3072
#define Ee 16
#define CAPc 160
#define Bbat 8
#define Nseq 2048

#define N1X 3328            // GEMM1 N: 3072 z + 256 u1
#define N2X 1024            // GEMM2 N: 768 w + 256 u2

// Output layout (float32, concatenated in reference return order)
#define OFF_AUX    12582912
#define OFF_BAL    12582913
#define OFF_ZL     12582914
#define OFF_LOGITS 12582915ll
#define OFF_ENERGY 12845059ll
#define OFF_GIDX   12861443ll

// ---------------- scratch (device globals; no runtime allocation) ----------------
__device__ float g_wi[(size_t)Tn * Dd];                 // RMS-normed input (fp32, for logits)
__device__ float g_hx[(size_t)Tn * Ff];                 // z raw (fp32)
__device__ float g_wx[(size_t)Tn * Dd];                 // w raw (fp32)
__device__ __half g_A1 [(size_t)Tn * Dd];               // wi fp16
__device__ __half g_B1x[(size_t)N1X * Dd];              // [Wi | Ai cols] fp16
__device__ __half g_A2 [(size_t)Tn * Ff];               // h fp16
__device__ __half g_B2x[(size_t)N2X * Ff];              // [Wo | Ao cols] fp16
__device__ __half g_V1 [(size_t)Tn * 256];              // gated u1 fp16
__device__ __half g_V2 [(size_t)Tn * 256];              // gated u2 fp16
__device__ __half g_Bd1[(size_t)Ff * 256];              // Bi^T fp16
__device__ __half g_Bd2[(size_t)Dd * 256];              // Bo^T fp16
__device__ int   g_e  [2 * Tn];
__device__ float g_gate[2 * Tn];
__device__ float g_gp  [2 * Tn];                        // gate after drop (0 if dropped)
__device__ int   g_sh1 [Tn];
__device__ float g_dp[Bbat * Ee];
__device__ float g_d1[Bbat * Ee];
__device__ float g_zl;

// ---------------- PTX helpers (sm_100-safe) ----------------
__device__ __forceinline__ uint32_t s2u(const void* p) {
    uint32_t a;
    asm("{ .reg .u64 t; cvta.to.shared.u64 t, %1; cvt.u32.u64 %0, t; }" : "=r"(a) : "l"(p));
    return a;
}
__device__ __forceinline__ void cpa16(uint32_t s, const void* g) {
    asm volatile("cp.async.cg.shared.global [%0], [%1], 16;\n" :: "r"(s), "l"(g));
}
#define CPA_COMMIT() asm volatile("cp.async.commit_group;\n" ::: "memory")
#define CPA_WAIT1()  asm volatile("cp.async.wait_group 1;\n" ::: "memory")

__device__ __forceinline__ void ldsm4(uint32_t* r, uint32_t a) {
    asm volatile("ldmatrix.sync.aligned.m8n8.x4.shared.b16 {%0,%1,%2,%3}, [%4];"
                 : "=r"(r[0]), "=r"(r[1]), "=r"(r[2]), "=r"(r[3]) : "r"(a));
}
__device__ __forceinline__ void mma16816(float* c, const uint32_t* a, uint32_t b0, uint32_t b1) {
    asm volatile("mma.sync.aligned.m16n8k16.row.col.f32.f16.f16.f32 "
                 "{%0,%1,%2,%3}, {%4,%5,%6,%7}, {%8,%9}, {%0,%1,%2,%3};"
                 : "+f"(c[0]), "+f"(c[1]), "+f"(c[2]), "+f"(c[3])
                 : "r"(a[0]), "r"(a[1]), "r"(a[2]), "r"(a[3]), "r"(b0), "r"(b1));
}

#define SWZ(o) ((o) ^ (((o) >> 3) & 0x70))

// GEMM smem: A stages [128][64]fp16 = 16KB (x3), B stages same
#define SMEM_GEMM 98304

// ---------------- single-pass fp16 GEMM: C[m,n] = sum_k A[m,k]*B[n,k] ----------------
// Tile 128x128, K-chunk 64, 3-stage cp.async, 256 threads, 2 CTAs/SM, single sync/chunk.
// Requires KI >= 3 (well, >= 2 prologue chunks; KI>=4 in all uses).
// mode 0: raw store to C (stride Nmain) for bn < Nmain; gated-V fp16 to vout for bn >= Nmain
// mode 1: h-epilogue: z=aux1 (stride Nmain); h=relu(z)+gs*z+acc; write hout fp16 (stride Nmain)
// mode 2: out-epilogue: C = aux1(x) + (1+gs)*aux2(w) + acc; all stride Nmain
__global__ __launch_bounds__(256, 2)
void k_tc_gemm(const __half* __restrict__ A, const __half* __restrict__ B,
               float* __restrict__ C, int Kst, int KI, int mode, int Nmain,
               const float* __restrict__ aux1, const float* __restrict__ aux2,
               __half* __restrict__ hout, __half* __restrict__ vout) {
    extern __shared__ char smem[];
    const uint32_t sb = s2u(smem);
    const int tid = threadIdx.x;
    const int wid = tid >> 5;
    const int lane = tid & 31;
    const int warp_m = wid & 1;          // 2 groups of M=64
    const int warp_n = wid >> 1;         // 4 groups of N=32
    const int bm = blockIdx.y * 128;
    const int bn = blockIdx.x * 128;

    // ---- loader precompute ----
    const __half* agp[4];
    const __half* bgp[4];
    uint32_t asm_[4], bsm_[4];
    #pragma unroll
    for (int j = 0; j < 4; j++) {
        int idx = tid + 256 * j, row = idx >> 3, seg = idx & 7;
        agp[j] = A + (size_t)(bm + row) * Kst + seg * 8;
        bgp[j] = B + (size_t)(bn + row) * Kst + seg * 8;
        uint32_t so = SWZ(row * 128 + seg * 16);
        asm_[j] = sb + so;
        bsm_[j] = sb + 49152 + so;
    }

    // ---- compute precompute: row offsets + swizzle XOR masks ----
    const uint32_t hiA = (lane >> 4) << 4;
    const uint32_t hiB = ((lane >> 3) & 1) << 4;
    uint32_t aro[4], axm[4];
    #pragma unroll
    for (int mt = 0; mt < 4; mt++) {
        int row = warp_m * 64 + mt * 16 + (lane & 15);
        aro[mt] = row * 128;
        axm[mt] = (row & 7) << 4;
    }
    uint32_t bro[2], bxm[2];
    #pragma unroll
    for (int g = 0; g < 2; g++) {
        int nr = warp_n * 32 + g * 16 + ((lane >> 4) << 3) + (lane & 7);
        bro[g] = nr * 128;
        bxm[g] = (nr & 7) << 4;
    }

    float acc[4][4][4];
    #pragma unroll
    for (int i = 0; i < 4; i++)
        #pragma unroll
        for (int j = 0; j < 4; j++)
            #pragma unroll
            for (int q = 0; q < 4; q++) acc[i][j][q] = 0.f;

    // prologue: chunks 0,1
    #pragma unroll
    for (int c = 0; c < 2; c++) {
        #pragma unroll
        for (int j = 0; j < 4; j++) cpa16(asm_[j] + c * 16384, agp[j] + c * 64);
        #pragma unroll
        for (int j = 0; j < 4; j++) cpa16(bsm_[j] + c * 16384, bgp[j] + c * 64);
        CPA_COMMIT();
    }

    int si = 0;       // compute stage
    int sj = 2;       // prefetch stage
    int kc = 128;     // k-offset of chunk i+2

    for (int i = 0; i < KI; i++) {
        CPA_WAIT1();
        __syncthreads();

        if (i + 2 < KI) {
            uint32_t soff = sj * 16384;
            #pragma unroll
            for (int jj = 0; jj < 4; jj++) cpa16(asm_[jj] + soff, agp[jj] + kc);
            #pragma unroll
            for (int jj = 0; jj < 4; jj++) cpa16(bsm_[jj] + soff, bgp[jj] + kc);
            kc += 64;
            sj = (sj == 2) ? 0 : sj + 1;
        }
        CPA_COMMIT();

        const uint32_t sbase = si * 16384;
        uint32_t saA[4], sBb[2];
        #pragma unroll
        for (int mt = 0; mt < 4; mt++) saA[mt] = sb + sbase + aro[mt];
        #pragma unroll
        for (int g = 0; g < 2; g++) sBb[g] = sb + 49152 + sbase + bro[g];
        si = (si == 2) ? 0 : si + 1;

        #pragma unroll
        for (int ks = 0; ks < 4; ks++) {
            uint32_t a[4][4];
            #pragma unroll
            for (int mt = 0; mt < 4; mt++)
                ldsm4(a[mt], saA[mt] + ((ks * 32 + hiA) ^ axm[mt]));
            uint32_t b[2][4];
            #pragma unroll
            for (int g = 0; g < 2; g++)
                ldsm4(b[g], sBb[g] + ((ks * 32 + hiB) ^ bxm[g]));
            #pragma unroll
            for (int mt = 0; mt < 4; mt++)
                #pragma unroll
                for (int nt = 0; nt < 4; nt++) {
                    int g = nt >> 1, hf = (nt & 1) << 1;
                    mma16816(acc[mt][nt], a[mt], b[g][hf], b[g][hf + 1]);
                }
        }
        // no trailing sync: next iteration's top sync protects stage reuse
    }

    if (mode == 0) {
        if (vout != nullptr && bn >= Nmain) {
            // gated-V epilogue: v = 2*g(token, expert(col))*acc, fp16
            const int bnv = bn - Nmain;
            #pragma unroll
            for (int mt = 0; mt < 4; mt++) {
                int r0 = bm + warp_m * 64 + mt * 16 + (lane >> 2);
                int eA0 = g_e[r0], eA1 = g_e[Tn + r0];
                float gA0 = g_gp[r0], gA1 = g_gp[Tn + r0];
                int eB0 = g_e[r0 + 8], eB1 = g_e[Tn + r0 + 8];
                float gB0 = g_gp[r0 + 8], gB1 = g_gp[Tn + r0 + 8];
                #pragma unroll
                for (int nt = 0; nt < 4; nt++) {
                    int vcol = bnv + warp_n * 32 + nt * 8 + (lane & 3) * 2;
                    int e = vcol >> 4;
                    float ga = (e == eA0) ? gA0 : (e == eA1) ? gA1 : 0.f;
                    float gb = (e == eB0) ? gB0 : (e == eB1) ? gB1 : 0.f;
                    *(half2*)(vout + (size_t)r0 * 256 + vcol) =
                        __floats2half2_rn(2.f * ga * acc[mt][nt][0], 2.f * ga * acc[mt][nt][1]);
                    *(half2*)(vout + (size_t)(r0 + 8) * 256 + vcol) =
                        __floats2half2_rn(2.f * gb * acc[mt][nt][2], 2.f * gb * acc[mt][nt][3]);
                }
            }
        } else {
            #pragma unroll
            for (int mt = 0; mt < 4; mt++) {
                int r0 = bm + warp_m * 64 + mt * 16 + (lane >> 2);
                #pragma unroll
                for (int nt = 0; nt < 4; nt++) {
                    int col = bn + warp_n * 32 + nt * 8 + (lane & 3) * 2;
                    *(float2*)(C + (size_t)r0 * Nmain + col)       = make_float2(acc[mt][nt][0], acc[mt][nt][1]);
                    *(float2*)(C + (size_t)(r0 + 8) * Nmain + col) = make_float2(acc[mt][nt][2], acc[mt][nt][3]);
                }
            }
        }
    } else if (mode == 1) {
        #pragma unroll
        for (int mt = 0; mt < 4; mt++) {
            int r0 = bm + warp_m * 64 + mt * 16 + (lane >> 2);
            float gsA = g_gp[r0] + g_gp[Tn + r0];
            float gsB = g_gp[r0 + 8] + g_gp[Tn + r0 + 8];
            #pragma unroll
            for (int nt = 0; nt < 4; nt++) {
                int col = bn + warp_n * 32 + nt * 8 + (lane & 3) * 2;
                float2 zA = *(const float2*)(aux1 + (size_t)r0 * Nmain + col);
                float2 zB = *(const float2*)(aux1 + (size_t)(r0 + 8) * Nmain + col);
                float h0 = fmaxf(zA.x, 0.f) + gsA * zA.x + acc[mt][nt][0];
                float h1 = fmaxf(zA.y, 0.f) + gsA * zA.y + acc[mt][nt][1];
                float h2 = fmaxf(zB.x, 0.f) + gsB * zB.x + acc[mt][nt][2];
                float h3 = fmaxf(zB.y, 0.f) + gsB * zB.y + acc[mt][nt][3];
                *(half2*)(hout + (size_t)r0 * Nmain + col)       = __floats2half2_rn(h0, h1);
                *(half2*)(hout + (size_t)(r0 + 8) * Nmain + col) = __floats2half2_rn(h2, h3);
            }
        }
    } else {
        #pragma unroll
        for (int mt = 0; mt < 4; mt++) {
            int r0 = bm + warp_m * 64 + mt * 16 + (lane >> 2);
            float gsA = 1.f + g_gp[r0] + g_gp[Tn + r0];
            float gsB = 1.f + g_gp[r0 + 8] + g_gp[Tn + r0 + 8];
            #pragma unroll
            for (int nt = 0; nt < 4; nt++) {
                int col = bn + warp_n * 32 + nt * 8 + (lane & 3) * 2;
                float2 wA = *(const float2*)(aux2 + (size_t)r0 * Nmain + col);
                float2 wB = *(const float2*)(aux2 + (size_t)(r0 + 8) * Nmain + col);
                float2 xA = *(const float2*)(aux1 + (size_t)r0 * Nmain + col);
                float2 xB = *(const float2*)(aux1 + (size_t)(r0 + 8) * Nmain + col);
                *(float2*)(C + (size_t)r0 * Nmain + col) = make_float2(
                    xA.x + gsA * wA.x + acc[mt][nt][0], xA.y + gsA * wA.y + acc[mt][nt][1]);
                *(float2*)(C + (size_t)(r0 + 8) * Nmain + col) = make_float2(
                    xB.x + gsB * wB.x + acc[mt][nt][2], xB.y + gsB * wB.y + acc[mt][nt][3]);
            }
        }
    }
}

// ---------------- RMS norm (+ fp16 A1 build + accumulator init fold) ------------
__global__ __launch_bounds__(256) void k_rms(const float* __restrict__ x,
                                             const float* __restrict__ lnw) {
    if (blockIdx.x == 0) {
        if (threadIdx.x < Bbat * Ee) g_dp[threadIdx.x] = 0.f;
        if (threadIdx.x == 0) g_zl = 0.f;
    }
    int t = blockIdx.x;
    const float* xr = x + (size_t)t * Dd;
    float s = 0.f;
    for (int d = threadIdx.x; d < Dd; d += 256) { float v = xr[d]; s += v * v; }
    __shared__ float red[256];
    red[threadIdx.x] = s; __syncthreads();
    for (int o = 128; o > 0; o >>= 1) {
        if (threadIdx.x < o) red[threadIdx.x] += red[threadIdx.x + o];
        __syncthreads();
    }
    float inv = rsqrtf(red[0] / (float)Dd + 1e-6f);
    for (int d = threadIdx.x; d < Dd; d += 256) {
        float v = xr[d] * inv * lnw[d];
        g_wi[(size_t)t * Dd + d] = v;
        g_A1[(size_t)t * Dd + d] = __float2half_rn(v);
    }
}

// ---------------- B1x build: rows 0..3071 = Wi, rows 3072.. = Ai cols ----------------
__global__ __launch_bounds__(256) void k_splitB1x(const float* __restrict__ Wi,
                                                  const float* __restrict__ Ai) {
    int n = blockIdx.x;
    __half* b = g_B1x + (size_t)n * Dd;
    if (n < Ff) {
        const float* wr = Wi + (size_t)n * Dd;
        for (int d = threadIdx.x; d < Dd; d += 256)
            b[d] = __float2half_rn(wr[d]);
    } else {
        int c = n - Ff, e = c >> 4, r = c & 15;
        const float* Ae = Ai + (size_t)e * Dd * 16 + r;
        for (int d = threadIdx.x; d < Dd; d += 256)
            b[d] = __float2half_rn(Ae[d * 16]);
    }
}

// ---------------- B2x build: rows 0..767 = Wo, rows 768.. = Ao cols ----------------
__global__ __launch_bounds__(256) void k_splitB2x(const float* __restrict__ Wo,
                                                  const float* __restrict__ Ao) {
    int n = blockIdx.x;
    __half* b = g_B2x + (size_t)n * Ff;
    if (n < Dd) {
        const float* wr = Wo + (size_t)n * Ff;
        for (int f = threadIdx.x; f < Ff; f += 256)
            b[f] = __float2half_rn(wr[f]);
    } else {
        int c = n - Dd, e = c >> 4, r = c & 15;
        const float* Ae = Ao + (size_t)e * Ff * 16 + r;
        for (int f = threadIdx.x; f < Ff; f += 256)
            b[f] = __float2half_rn(Ae[f * 16]);
    }
}

// ---------------- Bd1 build: row f, col c=(e*16+r) -> Bi[e,r,f] ----------------
__global__ __launch_bounds__(256) void k_splitBd1(const float* __restrict__ Bi) {
    int f = blockIdx.x;
    int c = threadIdx.x;
    if (c < 256) {
        int e = c >> 4, r = c & 15;
        g_Bd1[(size_t)f * 256 + c] = __float2half_rn(Bi[(size_t)e * 16 * Ff + (size_t)r * Ff + f]);
    }
}
// ---------------- Bd2 build: row d, col c=(e*16+r) -> Bo[e,r,d] ----------------
__global__ __launch_bounds__(256) void k_splitBd2(const float* __restrict__ Bo) {
    int d = blockIdx.x;
    int c = threadIdx.x;
    if (c < 256) {
        int e = c >> 4, r = c & 15;
        g_Bd2[(size_t)d * 256 + c] = __float2half_rn(Bo[(size_t)e * 16 * Dd + (size_t)r * Dd + d]);
    }
}

// ---------------- logits = wi_in @ Wg^T (float4 smem; fp32 — routing must be exact) --
__global__ __launch_bounds__(256) void k_logits(const float* __restrict__ Wg,
                                                float* __restrict__ out) {
    __shared__ float4 sWg[(Dd / 4) * 16];
    for (int i = threadIdx.x; i < Dd * 16 / 4; i += 256) {
        int d4 = i / 16, e = i % 16;
        const float* w = Wg + (size_t)e * Dd + d4 * 4;
        sWg[d4 * 16 + e] = make_float4(w[0], w[1], w[2], w[3]);
    }
    __syncthreads();
    int tok = blockIdx.x * 16 + (threadIdx.x >> 4);
    int e = threadIdx.x & 15;
    const float4* wr = (const float4*)(g_wi + (size_t)tok * Dd);
    float s = 0.f;
    #pragma unroll 4
    for (int d4 = 0; d4 < Dd / 4; d4++) {
        float4 xv = wr[d4];
        float4 wv = sWg[d4 * 16 + e];
        s += xv.x * wv.x + xv.y * wv.y + xv.z * wv.z + xv.w * wv.w;
    }
    out[OFF_LOGITS + (size_t)tok * 16 + e] = s;
}

// ---------------- softmax / top2 / gates / aux partials ----------------
__global__ __launch_bounds__(256) void k_gate(const float* __restrict__ rp,
                                              float* __restrict__ out) {
    int t = blockIdx.x * 256 + threadIdx.x;
    int lane = threadIdx.x & 31;
    const float* lg = out + OFF_LOGITS + (size_t)t * 16;
    float l[16];
    float mx = -1e30f;
    #pragma unroll
    for (int e = 0; e < 16; e++) { l[e] = lg[e]; mx = fmaxf(mx, l[e]); }
    float se = 0.f;
    #pragma unroll
    for (int e = 0; e < 16; e++) se += __expf(l[e] - mx);
    float lse = mx + __logf(se);
    out[OFF_ENERGY + t] = -lse;

    int e0 = 0; float b0 = l[0];
    #pragma unroll
    for (int e = 1; e < 16; e++) if (l[e] > b0) { b0 = l[e]; e0 = e; }
    int e1 = -1; float b1 = -1e30f;
    #pragma unroll
    for (int e = 0; e < 16; e++) if (e != e0 && l[e] > b1) { b1 = l[e]; e1 = e; }
    float v0 = __expf(b0 - lse), v1 = __expf(b1 - lse);
    float den = v0 + v1; if (den < 1e-9f) den = 1e-9f;
    float G0 = v0 / den, G1 = v1 / den;
    g_e[t] = e0; g_e[Tn + t] = e1;
    g_gate[t] = G0; g_gate[Tn + t] = G1;
    g_sh1[t] = (rp[Tn + t] < G1 * 5.0f) ? 1 : 0;

    int b = t >> 11;
    float zv = lse * lse;
    #pragma unroll
    for (int o = 16; o > 0; o >>= 1) zv += __shfl_xor_sync(0xffffffffu, zv, o);
    if (lane == 0) atomicAdd(&g_zl, zv);
    #pragma unroll
    for (int e = 0; e < 16; e++) {
        float pv = __expf(l[e] - lse);
        #pragma unroll
        for (int o = 16; o > 0; o >>= 1) pv += __shfl_xor_sync(0xffffffffu, pv, o);
        if (lane == 0) atomicAdd(&g_dp[b * 16 + e], pv);
    }
}

// ---------------- capacity scan: 16 threads per batch, thread e owns expert e --------
__global__ void k_scan(float* __restrict__ out) {
    int b = blockIdx.x;
    int e = threadIdx.x;            // 0..15
    int base = b * Nseq;
    int cnt = 0;
    for (int n = 0; n < Nseq; n += 4) {
        int4 ev = *(const int4*)(g_e + base + n);
        #pragma unroll
        for (int j = 0; j < 4; j++) {
            int et = (j == 0) ? ev.x : (j == 1) ? ev.y : (j == 2) ? ev.z : ev.w;
            if (et == e) {
                int t = base + n + j;
                bool s = cnt < CAPc;
                cnt++;
                g_gp[t] = s ? g_gate[t] : 0.f;
                out[OFF_GIDX + t] = s ? (float)e : 0.f;
            }
        }
    }
    int sv = cnt < CAPc ? cnt : CAPc;
    g_d1[b * 16 + e] = (float)sv / (float)Nseq;
    int cnt1 = sv;
    for (int n = 0; n < Nseq; n += 4) {
        int4 ev = *(const int4*)(g_e + Tn + base + n);
        int4 sh = *(const int4*)(g_sh1 + base + n);
        #pragma unroll
        for (int j = 0; j < 4; j++) {
            int et = (j == 0) ? ev.x : (j == 1) ? ev.y : (j == 2) ? ev.z : ev.w;
            int sj = (j == 0) ? sh.x : (j == 1) ? sh.y : (j == 2) ? sh.z : sh.w;
            if (et == e) {
                int t = base + n + j;
                if (sj) {
                    bool s = cnt1 < CAPc;
                    cnt1++;
                    g_gp[Tn + t] = s ? g_gate[Tn + t] : 0.f;
                    out[OFF_GIDX + Tn + t] = s ? (float)e : 0.f;
                } else {
                    g_gp[Tn + t] = 0.f;
                    out[OFF_GIDX + Tn + t] = 0.f;
                }
            }
        }
    }
}

// ---------------- aux scalars ----------------
__global__ void k_aux(float* __restrict__ out) {
    __shared__ float red[128];
    int i = threadIdx.x;
    red[i] = (g_dp[i] / (float)Nseq) * g_d1[i];
    __syncthreads();
    for (int o = 64; o > 0; o >>= 1) {
        if (i < o) red[i] += red[i + o];
        __syncthreads();
    }
    if (i == 0) {
        float bal = red[0] * 2.0f;
        float zl = g_zl / (float)Tn;
        out[OFF_BAL] = bal;
        out[OFF_ZL] = zl;
        out[OFF_AUX] = 0.01f * bal + 0.01f * zl;
    }
}

// ---------------- launch ----------------
extern "C" void kernel_launch(void* const* d_in, const int* in_sizes, int n_in,
                              void* d_out, int out_size) {
    const float* x   = (const float*)d_in[0];
    const float* rp  = (const float*)d_in[1];
    const float* lnw = (const float*)d_in[2];
    const float* Wg  = (const float*)d_in[3];
    const float* Wi  = (const float*)d_in[4];
    const float* Wo  = (const float*)d_in[5];
    const float* Ai  = (const float*)d_in[6];
    const float* Bi  = (const float*)d_in[7];
    const float* Ao  = (const float*)d_in[8];
    const float* Bo  = (const float*)d_in[9];
    float* out = (float*)d_out;

    cudaFuncSetAttribute(k_tc_gemm, cudaFuncAttributeMaxDynamicSharedMemorySize, SMEM_GEMM);

    __half *A1p, *B1xp, *A2p, *B2xp, *V1p, *V2p, *Bd1p, *Bd2p;
    float *hxp, *wxp;
    cudaGetSymbolAddress((void**)&A1p,  g_A1);
    cudaGetSymbolAddress((void**)&B1xp, g_B1x);
    cudaGetSymbolAddress((void**)&A2p,  g_A2);
    cudaGetSymbolAddress((void**)&B2xp, g_B2x);
    cudaGetSymbolAddress((void**)&V1p,  g_V1);
    cudaGetSymbolAddress((void**)&V2p,  g_V2);
    cudaGetSymbolAddress((void**)&Bd1p, g_Bd1);
    cudaGetSymbolAddress((void**)&Bd2p, g_Bd2);
    cudaGetSymbolAddress((void**)&hxp,  g_hx);
    cudaGetSymbolAddress((void**)&wxp,  g_wx);

    // prep + gating (gating precedes GEMM1 so its epilogue can gate the V columns)
    k_rms<<<Tn, 256>>>(x, lnw);
    k_splitB1x<<<N1X, 256>>>(Wi, Ai);
    k_splitB2x<<<N2X, 256>>>(Wo, Ao);
    k_logits<<<Tn / 16, 256>>>(Wg, out);
    k_gate<<<Tn / 256, 256>>>(rp, out);
    k_scan<<<Bbat, 16>>>(out);
    k_aux<<<1, 128>>>(out);

    // GEMM1: [z | gated u1->V1] = A1 @ B1x^T ; z -> g_hx (stride 3072)
    k_tc_gemm<<<dim3(N1X / 128, Tn / 128), 256, SMEM_GEMM>>>(
        A1p, B1xp, hxp, Dd, Dd / 64, 0, Ff, nullptr, nullptr, nullptr, V1p);
    k_splitBd1<<<Ff, 256>>>(Bi);
    // delta1: h = relu(z)+gs*z + V1@Bd1^T -> A2 fp16
    k_tc_gemm<<<dim3(Ff / 128, Tn / 128), 256, SMEM_GEMM>>>(
        V1p, Bd1p, nullptr, 256, 4, 1, Ff, hxp, nullptr, A2p, nullptr);
    k_splitBd2<<<Dd, 256>>>(Bo);
    // GEMM2: [w | gated u2->V2] = A2 @ B2x^T ; w -> g_wx (stride 768)
    k_tc_gemm<<<dim3(N2X / 128, Tn / 128), 256, SMEM_GEMM>>>(
        A2p, B2xp, wxp, Ff, Ff / 64, 0, Dd, nullptr, nullptr, nullptr, V2p);
    // delta2: out = x + (1+gs)*w + V2@Bd2^T
    k_tc_gemm<<<dim3(Dd / 128, Tn / 128), 256, SMEM_GEMM>>>(
        V2p, Bd2p, out, 256, 4, 2, Dd, x, wxp, nullptr, nullptr);
}